// round 1
// baseline (speedup 1.0000x reference)
#include <cuda_runtime.h>
#include <cstdint>

// ---------------- problem constants ----------------
#define NROWS 50000
#define MROWS 20000
#define FIN   256
#define HID   256
#define OUTF  64
#define NNZ_HHT 1600000
#define NNZ_H   1000000
#define NNZ_HT  1000000
#define NNZ_HTH 640000
#define NEG_SLOPE 0.2f

// ---------------- scratch layout (floats) ----------------
// xw0      [N,256]   @ 0
// yw0      [M,256]   @ 12800000
// acc_hht  [N,256]   @ 17920000
// acc_h    [N,256]   @ 30720000
// acc_ht   [M,256]   @ 43520000
// acc_hth  [M,256]   @ 48640000
// x1w1     [N,64]    @ 53760000
// y1w1     [M,64]    @ 56960000
// acc1_hht [N,64]    @ 58240000
// acc1_h   [N,64]    @ 61440000
// acc1_ht  [M,64]    @ 64640000
// acc1_hth [M,64]    @ 65920000
// total 67200000 floats = 268.8 MB
#define O_XW0      0L
#define O_YW0      12800000L
#define O_ACC_HHT  17920000L
#define O_ACC_H    30720000L
#define O_ACC_HT   43520000L
#define O_ACC_HTH  48640000L
#define O_X1W1     53760000L
#define O_Y1W1     56960000L
#define O_ACC1_HHT 58240000L
#define O_ACC1_H   61440000L
#define O_ACC1_HT  64640000L
#define O_ACC1_HTH 65920000L
#define SCRATCH_FLOATS 67200000L

__device__ __align__(16) float g_scratch[SCRATCH_FLOATS];

__device__ __forceinline__ float leaky(float v) {
    return v >= 0.f ? v : NEG_SLOPE * v;
}

__device__ __forceinline__ void red_add_v4(float* addr, float4 v) {
    asm volatile("red.global.add.v4.f32 [%0], {%1,%2,%3,%4};"
                 :: "l"(addr), "f"(v.x), "f"(v.y), "f"(v.z), "f"(v.w)
                 : "memory");
}

// ---------------- zero-fill ----------------
__global__ void zero_k(float4* __restrict__ p, int n4) {
    int i = blockIdx.x * blockDim.x + threadIdx.x;
    if (i < n4) p[i] = make_float4(0.f, 0.f, 0.f, 0.f);
}

// ---------------- dense GEMM:  C[Rows,Ncols] = act(A) @ W,  K = 256 ----------------
// FUSED=0: A = A1.  FUSED=1: A = leaky(A1) + leaky(A2).
// Block: 256 threads, tile 64x64, BK=16, 4x4 micro-tile per thread.
template<int FUSED>
__global__ void gemm_k256(const float* __restrict__ A1, const float* __restrict__ A2,
                          const float* __restrict__ W, float* __restrict__ C,
                          int Rows, int Ncols) {
    const int BM = 64, BN = 64, BK = 16;
    __shared__ __align__(16) float As[BM][BK + 1];   // padded to dodge bank conflicts
    __shared__ __align__(16) float Ws[BK][BN];

    int tid = threadIdx.x;
    int tx = tid & 15;          // 0..15 -> N micro-tile
    int ty = tid >> 4;          // 0..15 -> M micro-tile
    int m0 = blockIdx.y * BM;
    int n0 = blockIdx.x * BN;

    float acc[4][4] = {};

    for (int k0 = 0; k0 < 256; k0 += BK) {
        // --- load A tile (64 rows x 16 k) : one float4 per thread ---
        {
            int m  = tid >> 2;          // 0..63
            int kq = tid & 3;           // 0..3
            int gm = m0 + m;
            float4 a = make_float4(0.f, 0.f, 0.f, 0.f);
            if (gm < Rows) {
                long base = (long)gm * 256 + k0 + kq * 4;
                float4 v1 = *(const float4*)(A1 + base);
                if (FUSED) {
                    float4 v2 = *(const float4*)(A2 + base);
                    a.x = leaky(v1.x) + leaky(v2.x);
                    a.y = leaky(v1.y) + leaky(v2.y);
                    a.z = leaky(v1.z) + leaky(v2.z);
                    a.w = leaky(v1.w) + leaky(v2.w);
                } else {
                    a = v1;
                }
            }
            As[m][kq * 4 + 0] = a.x;
            As[m][kq * 4 + 1] = a.y;
            As[m][kq * 4 + 2] = a.z;
            As[m][kq * 4 + 3] = a.w;
        }
        // --- load W tile (16 k x 64 n) : one float4 per thread ---
        {
            int k  = tid >> 4;          // 0..15
            int nq = tid & 15;          // 0..15
            float4 w = *(const float4*)(W + (long)(k0 + k) * Ncols + n0 + nq * 4);
            *(float4*)&Ws[k][nq * 4] = w;
        }
        __syncthreads();

        #pragma unroll
        for (int k = 0; k < BK; k++) {
            float ra0 = As[ty * 4 + 0][k];
            float ra1 = As[ty * 4 + 1][k];
            float ra2 = As[ty * 4 + 2][k];
            float ra3 = As[ty * 4 + 3][k];
            float4 rb = *(float4*)&Ws[k][tx * 4];
            acc[0][0] += ra0 * rb.x; acc[0][1] += ra0 * rb.y; acc[0][2] += ra0 * rb.z; acc[0][3] += ra0 * rb.w;
            acc[1][0] += ra1 * rb.x; acc[1][1] += ra1 * rb.y; acc[1][2] += ra1 * rb.z; acc[1][3] += ra1 * rb.w;
            acc[2][0] += ra2 * rb.x; acc[2][1] += ra2 * rb.y; acc[2][2] += ra2 * rb.z; acc[2][3] += ra2 * rb.w;
            acc[3][0] += ra3 * rb.x; acc[3][1] += ra3 * rb.y; acc[3][2] += ra3 * rb.z; acc[3][3] += ra3 * rb.w;
        }
        __syncthreads();
    }

    #pragma unroll
    for (int i = 0; i < 4; i++) {
        int gm = m0 + ty * 4 + i;
        if (gm < Rows) {
            float4 r = make_float4(acc[i][0], acc[i][1], acc[i][2], acc[i][3]);
            *(float4*)(C + (long)gm * Ncols + n0 + tx * 4) = r;
        }
    }
}

// ---------------- SpMM scatter, F=256: one warp per nnz ----------------
__global__ void spmm_f256(const int* __restrict__ rows, const int* __restrict__ cols,
                          const float* __restrict__ vals, const float* __restrict__ dense,
                          float* __restrict__ out, int nnz) {
    int warp = (blockIdx.x * blockDim.x + threadIdx.x) >> 5;
    int lane = threadIdx.x & 31;
    if (warp >= nnz) return;
    int r = rows[warp];
    int c = cols[warp];
    float v = vals[warp];
    const float4* src = (const float4*)(dense + (long)c * 256);
    float* dst = out + (long)r * 256;
    #pragma unroll
    for (int p = 0; p < 2; p++) {
        float4 d = src[lane + p * 32];
        d.x *= v; d.y *= v; d.z *= v; d.w *= v;
        red_add_v4(dst + (lane + p * 32) * 4, d);
    }
}

// ---------------- SpMM scatter, F=64: one warp per 2 nnz ----------------
__global__ void spmm_f64(const int* __restrict__ rows, const int* __restrict__ cols,
                         const float* __restrict__ vals, const float* __restrict__ dense,
                         float* __restrict__ out, int nnz) {
    int warp = (blockIdx.x * blockDim.x + threadIdx.x) >> 5;
    int lane = threadIdx.x & 31;
    long e = (long)warp * 2 + (lane >> 4);
    if (e >= nnz) return;
    int sub = lane & 15;
    int r = rows[e];
    int c = cols[e];
    float v = vals[e];
    float4 d = ((const float4*)(dense + (long)c * 64))[sub];
    d.x *= v; d.y *= v; d.z *= v; d.w *= v;
    red_add_v4(out + (long)r * 64 + sub * 4, d);
}

// ---------------- final combine: out = leaky(a) + leaky(b) ----------------
__global__ void combine_k(const float4* __restrict__ a, const float4* __restrict__ b,
                          float4* __restrict__ o, int n4) {
    int i = blockIdx.x * blockDim.x + threadIdx.x;
    if (i >= n4) return;
    float4 va = a[i], vb = b[i];
    float4 r;
    r.x = leaky(va.x) + leaky(vb.x);
    r.y = leaky(va.y) + leaky(vb.y);
    r.z = leaky(va.z) + leaky(vb.z);
    r.w = leaky(va.w) + leaky(vb.w);
    o[i] = r;
}

extern "C" void kernel_launch(void* const* d_in, const int* in_sizes, int n_in,
                              void* d_out, int out_size) {
    const float* x  = (const float*)d_in[0];
    const float* y  = (const float*)d_in[1];
    const float* W0 = (const float*)d_in[2];
    const float* W1 = (const float*)d_in[3];
    const int*   hht_r = (const int*)d_in[4];
    const int*   hht_c = (const int*)d_in[5];
    const float* hht_v = (const float*)d_in[6];
    const int*   h_r = (const int*)d_in[7];
    const int*   h_c = (const int*)d_in[8];
    const float* h_v = (const float*)d_in[9];
    const int*   ht_r = (const int*)d_in[10];
    const int*   ht_c = (const int*)d_in[11];
    const float* ht_v = (const float*)d_in[12];
    const int*   hth_r = (const int*)d_in[13];
    const int*   hth_c = (const int*)d_in[14];
    const float* hth_v = (const float*)d_in[15];
    float* out = (float*)d_out;

    void* sp = nullptr;
    cudaGetSymbolAddress(&sp, g_scratch);
    float* S = (float*)sp;

    float* xw0      = S + O_XW0;
    float* yw0      = S + O_YW0;
    float* acc_hht  = S + O_ACC_HHT;
    float* acc_h    = S + O_ACC_H;
    float* acc_ht   = S + O_ACC_HT;
    float* acc_hth  = S + O_ACC_HTH;
    float* x1w1     = S + O_X1W1;
    float* y1w1     = S + O_Y1W1;
    float* acc1_hht = S + O_ACC1_HHT;
    float* acc1_h   = S + O_ACC1_H;
    float* acc1_ht  = S + O_ACC1_HT;
    float* acc1_hth = S + O_ACC1_HTH;

    const int T = 256;

    // zero the accumulators (layer0 accs are contiguous; layer1 accs are contiguous)
    {
        long n0 = (O_X1W1 - O_ACC_HHT) / 4;        // layer0 accs, in float4
        zero_k<<<(int)((n0 + T - 1) / T), T>>>((float4*)acc_hht, (int)n0);
        long n1 = (SCRATCH_FLOATS - O_ACC1_HHT) / 4; // layer1 accs, in float4
        zero_k<<<(int)((n1 + T - 1) / T), T>>>((float4*)acc1_hht, (int)n1);
    }

    // layer-0 dense GEMMs: xw0 = x @ W0 ; yw0 = y @ W0
    {
        dim3 gx(HID / 64, (NROWS + 63) / 64);
        gemm_k256<0><<<gx, T>>>(x, nullptr, W0, xw0, NROWS, HID);
        dim3 gy(HID / 64, (MROWS + 63) / 64);
        gemm_k256<0><<<gy, T>>>(y, nullptr, W0, yw0, MROWS, HID);
    }

    // layer-0 SpMM scatters (one warp per nnz; 8 warps per block)
    spmm_f256<<<(NNZ_HHT + 7) / 8, T>>>(hht_r, hht_c, hht_v, xw0, acc_hht, NNZ_HHT);
    spmm_f256<<<(NNZ_H   + 7) / 8, T>>>(h_r,   h_c,   h_v,   yw0, acc_h,   NNZ_H);
    spmm_f256<<<(NNZ_HT  + 7) / 8, T>>>(ht_r,  ht_c,  ht_v,  xw0, acc_ht,  NNZ_HT);
    spmm_f256<<<(NNZ_HTH + 7) / 8, T>>>(hth_r, hth_c, hth_v, yw0, acc_hth, NNZ_HTH);

    // layer-1 dense GEMMs with fused leaky+add on the input:
    //   x1w1 = (leaky(acc_hht)+leaky(acc_h)) @ W1 ; y1w1 likewise
    {
        dim3 gx(OUTF / 64, (NROWS + 63) / 64);
        gemm_k256<1><<<gx, T>>>(acc_hht, acc_h, W1, x1w1, NROWS, OUTF);
        dim3 gy(OUTF / 64, (MROWS + 63) / 64);
        gemm_k256<1><<<gy, T>>>(acc_ht, acc_hth, W1, y1w1, MROWS, OUTF);
    }

    // layer-1 SpMM scatters (two nnz per warp; 16 nnz per block)
    spmm_f64<<<(NNZ_HHT + 15) / 16, T>>>(hht_r, hht_c, hht_v, x1w1, acc1_hht, NNZ_HHT);
    spmm_f64<<<(NNZ_H   + 15) / 16, T>>>(h_r,   h_c,   h_v,   y1w1, acc1_h,   NNZ_H);
    spmm_f64<<<(NNZ_HT  + 15) / 16, T>>>(ht_r,  ht_c,  ht_v,  x1w1, acc1_ht,  NNZ_HT);
    spmm_f64<<<(NNZ_HTH + 15) / 16, T>>>(hth_r, hth_c, hth_v, y1w1, acc1_hth, NNZ_HTH);

    // final combine into d_out: x_out (N*64) then y_out (M*64)
    {
        int nx4 = NROWS * OUTF / 4;
        combine_k<<<(nx4 + T - 1) / T, T>>>((const float4*)acc1_hht, (const float4*)acc1_h,
                                            (float4*)out, nx4);
        int ny4 = MROWS * OUTF / 4;
        combine_k<<<(ny4 + T - 1) / T, T>>>((const float4*)acc1_ht, (const float4*)acc1_hth,
                                            (float4*)(out + (long)NROWS * OUTF), ny4);
    }
}

// round 3
// speedup vs baseline: 1.5323x; 1.5323x over previous
#include <cuda_runtime.h>
#include <cstdint>

// ---------------- problem constants ----------------
#define NROWS 50000
#define MROWS 20000
#define NNZ_HHT 1600000
#define NNZ_H   1000000
#define NNZ_HT  1000000
#define NNZ_HTH 640000
#define NNZ_TOT (NNZ_HHT + NNZ_H + NNZ_HT + NNZ_HTH)
#define NEG_SLOPE 0.2f

// ---------------- float scratch layout ----------------
#define O_XW0   0L                       // [N,256]
#define O_YW0   (O_XW0  + 12800000L)     // [M,256]
#define O_X1    (O_YW0  + 5120000L)      // [N,256]
#define O_Y1    (O_X1   + 12800000L)     // [M,256]
#define O_X1W1  (O_Y1   + 5120000L)      // [N,64]
#define O_Y1W1  (O_X1W1 + 3200000L)      // [M,64]
#define O_CVAL  (O_Y1W1 + 1280000L)      // [NNZ_TOT] CSR values (hht|h|ht|hth)
#define FS_TOT  (O_CVAL + (long)NNZ_TOT)

// ---------------- int scratch layout ----------------
#define I_CUR   0L                                   // cursors/counts: N,N,M,M
#define I_RP    (I_CUR + 2L*NROWS + 2L*MROWS)        // row_ptrs: N+1,N+1,M+1,M+1
#define I_CCOL  (I_RP  + 2L*(NROWS+1) + 2L*(MROWS+1))// CSR cols (hht|h|ht|hth)
#define IS_TOT  (I_CCOL + (long)NNZ_TOT)

// per-matrix offsets inside cursor / row_ptr / csr regions
#define CUR_HHT 0L
#define CUR_H   ((long)NROWS)
#define CUR_HT  (2L*NROWS)
#define CUR_HTH (2L*NROWS + MROWS)
#define RP_HHT  0L
#define RP_H    ((long)NROWS + 1)
#define RP_HT   (2L*(NROWS + 1))
#define RP_HTH  (2L*(NROWS + 1) + MROWS + 1)
#define CS_HHT  0L
#define CS_H    ((long)NNZ_HHT)
#define CS_HT   ((long)NNZ_HHT + NNZ_H)
#define CS_HTH  ((long)NNZ_HHT + NNZ_H + NNZ_HT)

__device__ __align__(16) float g_fs[FS_TOT];
__device__ __align__(16) int   g_is[IS_TOT];

__device__ __forceinline__ float leaky(float v) {
    return v >= 0.f ? v : NEG_SLOPE * v;
}

// ---------------- zero ints ----------------
__global__ void zero_i(int* __restrict__ p, int n) {
    int i = blockIdx.x * blockDim.x + threadIdx.x;
    if (i < n) p[i] = 0;
}

// ---------------- CSR build: count ----------------
__global__ void count_k(const int* __restrict__ rows, int nnz, int* __restrict__ cnt) {
    int i = blockIdx.x * blockDim.x + threadIdx.x;
    if (i < nnz) atomicAdd(&cnt[rows[i]], 1);
}

// ---------------- CSR build: scan (one block per matrix) ----------------
__global__ void scan_all_k(int* __restrict__ cur, int* __restrict__ rp) {
    __shared__ int sh[1024];
    __shared__ int carry;
    int b = blockIdx.x;
    int n;
    int* cnt;
    int* rowp;
    if (b == 0)      { n = NROWS; cnt = cur + CUR_HHT; rowp = rp + RP_HHT; }
    else if (b == 1) { n = NROWS; cnt = cur + CUR_H;   rowp = rp + RP_H;   }
    else if (b == 2) { n = MROWS; cnt = cur + CUR_HT;  rowp = rp + RP_HT;  }
    else             { n = MROWS; cnt = cur + CUR_HTH; rowp = rp + RP_HTH; }

    int tid = threadIdx.x;
    if (tid == 0) carry = 0;
    __syncthreads();
    for (int base = 0; base < n; base += 1024) {
        int i = base + tid;
        int v = (i < n) ? cnt[i] : 0;
        sh[tid] = v;
        __syncthreads();
        #pragma unroll
        for (int off = 1; off < 1024; off <<= 1) {
            int t = (tid >= off) ? sh[tid - off] : 0;
            __syncthreads();
            sh[tid] += t;
            __syncthreads();
        }
        int excl = carry + sh[tid] - v;
        if (i < n) { rowp[i] = excl; cnt[i] = excl; }
        __syncthreads();
        if (tid == 1023) carry += sh[1023];
        __syncthreads();
    }
    if (tid == 0) rowp[n] = carry;
}

// ---------------- CSR build: permute ----------------
__global__ void permute_k(const int* __restrict__ rows, const int* __restrict__ cols,
                          const float* __restrict__ vals, int nnz,
                          int* __restrict__ cursor, int* __restrict__ ccol,
                          float* __restrict__ cval) {
    int i = blockIdx.x * blockDim.x + threadIdx.x;
    if (i >= nnz) return;
    int r = rows[i];
    int slot = atomicAdd(&cursor[r], 1);
    ccol[slot] = cols[i];
    cval[slot] = vals[i];
}

// ---------------- dense GEMM:  C[Rows,Ncols] = A @ W,  K = 256 ----------------
__global__ void gemm_k256(const float* __restrict__ A, const float* __restrict__ W,
                          float* __restrict__ C, int Rows, int Ncols) {
    const int BM = 64, BN = 64, BK = 16;
    __shared__ __align__(16) float As[BM][BK + 1];
    __shared__ __align__(16) float Ws[BK][BN];

    int tid = threadIdx.x;
    int tx = tid & 15;
    int ty = tid >> 4;
    int m0 = blockIdx.y * BM;
    int n0 = blockIdx.x * BN;

    float acc[4][4] = {};

    for (int k0 = 0; k0 < 256; k0 += BK) {
        {
            int m  = tid >> 2;
            int kq = tid & 3;
            int gm = m0 + m;
            float4 a = make_float4(0.f, 0.f, 0.f, 0.f);
            if (gm < Rows)
                a = *(const float4*)(A + (long)gm * 256 + k0 + kq * 4);
            As[m][kq * 4 + 0] = a.x;
            As[m][kq * 4 + 1] = a.y;
            As[m][kq * 4 + 2] = a.z;
            As[m][kq * 4 + 3] = a.w;
        }
        {
            int k  = tid >> 4;
            int nq = tid & 15;
            float4 w = *(const float4*)(W + (long)(k0 + k) * Ncols + n0 + nq * 4);
            *(float4*)&Ws[k][nq * 4] = w;
        }
        __syncthreads();

        #pragma unroll
        for (int k = 0; k < BK; k++) {
            float ra0 = As[ty * 4 + 0][k];
            float ra1 = As[ty * 4 + 1][k];
            float ra2 = As[ty * 4 + 2][k];
            float ra3 = As[ty * 4 + 3][k];
            float4 rb = *(float4*)&Ws[k][tx * 4];
            acc[0][0] += ra0 * rb.x; acc[0][1] += ra0 * rb.y; acc[0][2] += ra0 * rb.z; acc[0][3] += ra0 * rb.w;
            acc[1][0] += ra1 * rb.x; acc[1][1] += ra1 * rb.y; acc[1][2] += ra1 * rb.z; acc[1][3] += ra1 * rb.w;
            acc[2][0] += ra2 * rb.x; acc[2][1] += ra2 * rb.y; acc[2][2] += ra2 * rb.z; acc[2][3] += ra2 * rb.w;
            acc[3][0] += ra3 * rb.x; acc[3][1] += ra3 * rb.y; acc[3][2] += ra3 * rb.z; acc[3][3] += ra3 * rb.w;
        }
        __syncthreads();
    }

    #pragma unroll
    for (int i = 0; i < 4; i++) {
        int gm = m0 + ty * 4 + i;
        if (gm < Rows) {
            float4 r = make_float4(acc[i][0], acc[i][1], acc[i][2], acc[i][3]);
            *(float4*)(C + (long)gm * Ncols + n0 + tx * 4) = r;
        }
    }
}

// ---------------- fused dual CSR SpMM + leaky epilogue, F=256 ----------------
// out[r] = leaky( sum_A ) + leaky( sum_B ), one warp per output row.
// Software-pipelined col/val fetch (depth 1) to cover index-load latency.
__device__ __forceinline__ void csr_row_accum_f256(
    const int* __restrict__ col, const float* __restrict__ val,
    int s, int e, const float* __restrict__ dense, int lane,
    float4& acc0, float4& acc1)
{
    if (s >= e) return;
    int c_next = __ldg(col + s);
    float v_next = __ldg(val + s);
    for (int j = s; j < e; j++) {
        int c = c_next;
        float v = v_next;
        if (j + 1 < e) {
            c_next = __ldg(col + j + 1);
            v_next = __ldg(val + j + 1);
        }
        const float4* src = (const float4*)(dense + (long)c * 256);
        float4 d0 = src[lane];
        float4 d1 = src[lane + 32];
        acc0.x += v * d0.x; acc0.y += v * d0.y; acc0.z += v * d0.z; acc0.w += v * d0.w;
        acc1.x += v * d1.x; acc1.y += v * d1.y; acc1.z += v * d1.z; acc1.w += v * d1.w;
    }
}

__global__ void spmm2_f256(const int* __restrict__ rpA, const int* __restrict__ colA,
                           const float* __restrict__ valA, const float* __restrict__ dA,
                           const int* __restrict__ rpB, const int* __restrict__ colB,
                           const float* __restrict__ valB, const float* __restrict__ dB,
                           float* __restrict__ outp, int nrows) {
    int w = (blockIdx.x * blockDim.x + threadIdx.x) >> 5;
    if (w >= nrows) return;
    int lane = threadIdx.x & 31;

    float4 a0 = make_float4(0,0,0,0), a1 = a0, b0 = a0, b1 = a0;

    csr_row_accum_f256(colA, valA, rpA[w], rpA[w + 1], dA, lane, a0, a1);
    csr_row_accum_f256(colB, valB, rpB[w], rpB[w + 1], dB, lane, b0, b1);

    float4 r0, r1;
    r0.x = leaky(a0.x) + leaky(b0.x); r0.y = leaky(a0.y) + leaky(b0.y);
    r0.z = leaky(a0.z) + leaky(b0.z); r0.w = leaky(a0.w) + leaky(b0.w);
    r1.x = leaky(a1.x) + leaky(b1.x); r1.y = leaky(a1.y) + leaky(b1.y);
    r1.z = leaky(a1.z) + leaky(b1.z); r1.w = leaky(a1.w) + leaky(b1.w);
    float4* dst = (float4*)(outp + (long)w * 256);
    dst[lane] = r0;
    dst[lane + 32] = r1;
}

// ---------------- fused dual CSR SpMM + leaky epilogue, F=64 ----------------
__global__ void spmm2_f64(const int* __restrict__ rpA, const int* __restrict__ colA,
                          const float* __restrict__ valA, const float* __restrict__ dA,
                          const int* __restrict__ rpB, const int* __restrict__ colB,
                          const float* __restrict__ valB, const float* __restrict__ dB,
                          float* __restrict__ outp, int nrows) {
    int w = (blockIdx.x * blockDim.x + threadIdx.x) >> 5;
    if (w >= nrows) return;
    int lane = threadIdx.x & 31;

    float2 a = make_float2(0, 0), b = a;

    int s = rpA[w], e = rpA[w + 1];
    for (int j = s; j < e; j++) {
        int c = __ldg(colA + j);
        float v = __ldg(valA + j);
        float2 d = ((const float2*)(dA + (long)c * 64))[lane];
        a.x += v * d.x; a.y += v * d.y;
    }
    s = rpB[w]; e = rpB[w + 1];
    for (int j = s; j < e; j++) {
        int c = __ldg(colB + j);
        float v = __ldg(valB + j);
        float2 d = ((const float2*)(dB + (long)c * 64))[lane];
        b.x += v * d.x; b.y += v * d.y;
    }

    float2 r;
    r.x = leaky(a.x) + leaky(b.x);
    r.y = leaky(a.y) + leaky(b.y);
    ((float2*)(outp + (long)w * 64))[lane] = r;
}

extern "C" void kernel_launch(void* const* d_in, const int* in_sizes, int n_in,
                              void* d_out, int out_size) {
    const float* x  = (const float*)d_in[0];
    const float* y  = (const float*)d_in[1];
    const float* W0 = (const float*)d_in[2];
    const float* W1 = (const float*)d_in[3];
    const int*   hht_r = (const int*)d_in[4];
    const int*   hht_c = (const int*)d_in[5];
    const float* hht_v = (const float*)d_in[6];
    const int*   h_r = (const int*)d_in[7];
    const int*   h_c = (const int*)d_in[8];
    const float* h_v = (const float*)d_in[9];
    const int*   ht_r = (const int*)d_in[10];
    const int*   ht_c = (const int*)d_in[11];
    const float* ht_v = (const float*)d_in[12];
    const int*   hth_r = (const int*)d_in[13];
    const int*   hth_c = (const int*)d_in[14];
    const float* hth_v = (const float*)d_in[15];
    float* out = (float*)d_out;

    void* p = nullptr;
    cudaGetSymbolAddress(&p, g_fs);
    float* F = (float*)p;
    cudaGetSymbolAddress(&p, g_is);
    int* I = (int*)p;

    float* xw0  = F + O_XW0;
    float* yw0  = F + O_YW0;
    float* x1   = F + O_X1;
    float* y1   = F + O_Y1;
    float* x1w1 = F + O_X1W1;
    float* y1w1 = F + O_Y1W1;
    float* cval = F + O_CVAL;

    int* cur  = I + I_CUR;
    int* rp   = I + I_RP;
    int* ccol = I + I_CCOL;

    const int T = 256;

    // ---- CSR build (atomics only on 140K small counters) ----
    {
        int ncur = 2 * NROWS + 2 * MROWS;
        zero_i<<<(ncur + T - 1) / T, T>>>(cur, ncur);

        count_k<<<(NNZ_HHT + T - 1) / T, T>>>(hht_r, NNZ_HHT, cur + CUR_HHT);
        count_k<<<(NNZ_H   + T - 1) / T, T>>>(h_r,   NNZ_H,   cur + CUR_H);
        count_k<<<(NNZ_HT  + T - 1) / T, T>>>(ht_r,  NNZ_HT,  cur + CUR_HT);
        count_k<<<(NNZ_HTH + T - 1) / T, T>>>(hth_r, NNZ_HTH, cur + CUR_HTH);

        scan_all_k<<<4, 1024>>>(cur, rp);

        permute_k<<<(NNZ_HHT + T - 1) / T, T>>>(hht_r, hht_c, hht_v, NNZ_HHT,
                                                cur + CUR_HHT, ccol + CS_HHT, cval + CS_HHT);
        permute_k<<<(NNZ_H + T - 1) / T, T>>>(h_r, h_c, h_v, NNZ_H,
                                              cur + CUR_H, ccol + CS_H, cval + CS_H);
        permute_k<<<(NNZ_HT + T - 1) / T, T>>>(ht_r, ht_c, ht_v, NNZ_HT,
                                               cur + CUR_HT, ccol + CS_HT, cval + CS_HT);
        permute_k<<<(NNZ_HTH + T - 1) / T, T>>>(hth_r, hth_c, hth_v, NNZ_HTH,
                                                cur + CUR_HTH, ccol + CS_HTH, cval + CS_HTH);
    }

    // ---- layer-0 dense GEMMs ----
    {
        dim3 gx(256 / 64, (NROWS + 63) / 64);
        gemm_k256<<<gx, T>>>(x, W0, xw0, NROWS, 256);
        dim3 gy(256 / 64, (MROWS + 63) / 64);
        gemm_k256<<<gy, T>>>(y, W0, yw0, MROWS, 256);
    }

    // ---- layer-0 fused SpMM (gather, no atomics) ----
    spmm2_f256<<<(NROWS + 7) / 8, T>>>(rp + RP_HHT, ccol + CS_HHT, cval + CS_HHT, xw0,
                                       rp + RP_H,   ccol + CS_H,   cval + CS_H,   yw0,
                                       x1, NROWS);
    spmm2_f256<<<(MROWS + 7) / 8, T>>>(rp + RP_HT,  ccol + CS_HT,  cval + CS_HT,  xw0,
                                       rp + RP_HTH, ccol + CS_HTH, cval + CS_HTH, yw0,
                                       y1, MROWS);

    // ---- layer-1 dense GEMMs ----
    {
        dim3 gx(64 / 64, (NROWS + 63) / 64);
        gemm_k256<<<gx, T>>>(x1, W1, x1w1, NROWS, 64);
        dim3 gy(64 / 64, (MROWS + 63) / 64);
        gemm_k256<<<gy, T>>>(y1, W1, y1w1, MROWS, 64);
    }

    // ---- layer-1 fused SpMM straight into d_out ----
    spmm2_f64<<<(NROWS + 7) / 8, T>>>(rp + RP_HHT, ccol + CS_HHT, cval + CS_HHT, x1w1,
                                      rp + RP_H,   ccol + CS_H,   cval + CS_H,   y1w1,
                                      out, NROWS);
    spmm2_f64<<<(MROWS + 7) / 8, T>>>(rp + RP_HT,  ccol + CS_HT,  cval + CS_HT,  x1w1,
                                      rp + RP_HTH, ccol + CS_HTH, cval + CS_HTH, y1w1,
                                      out + (long)NROWS * 64, MROWS);
}

// round 4
// speedup vs baseline: 1.7298x; 1.1289x over previous
#include <cuda_runtime.h>
#include <cuda_fp16.h>
#include <cstdint>

// ---------------- problem constants ----------------
#define NROWS 50000
#define MROWS 20000
#define NNZ_HHT 1600000
#define NNZ_H   1000000
#define NNZ_HT  1000000
#define NNZ_HTH 640000
#define NNZ_TOT (NNZ_HHT + NNZ_H + NNZ_HT + NNZ_HTH)
#define NEG_SLOPE 0.2f

// ---------------- float-unit scratch layout ----------------
// xw0  : [N,256] half  -> 6,400,000 float units
// yw0  : [M,256] half  -> 2,560,000
// x1   : [N,256] float -> 12,800,000
// y1   : [M,256] float -> 5,120,000
// x1w1 : [N,64]  half  -> 1,600,000
// y1w1 : [M,64]  half  -> 640,000
// cval : [NNZ_TOT] float
#define O_XW0   0L
#define O_YW0   (O_XW0  + 6400000L)
#define O_X1    (O_YW0  + 2560000L)
#define O_Y1    (O_X1   + 12800000L)
#define O_X1W1  (O_Y1   + 5120000L)
#define O_Y1W1  (O_X1W1 + 1600000L)
#define O_CVAL  (O_Y1W1 + 640000L)
#define FS_TOT  (O_CVAL + (long)NNZ_TOT)

// ---------------- int scratch layout ----------------
#define I_CUR   0L
#define I_RP    (I_CUR + 2L*NROWS + 2L*MROWS)
#define I_CCOL  (I_RP  + 2L*(NROWS+1) + 2L*(MROWS+1))
#define IS_TOT  (I_CCOL + (long)NNZ_TOT)

#define CUR_HHT 0L
#define CUR_H   ((long)NROWS)
#define CUR_HT  (2L*NROWS)
#define CUR_HTH (2L*NROWS + MROWS)
#define RP_HHT  0L
#define RP_H    ((long)NROWS + 1)
#define RP_HT   (2L*(NROWS + 1))
#define RP_HTH  (2L*(NROWS + 1) + MROWS + 1)
#define CS_HHT  0L
#define CS_H    ((long)NNZ_HHT)
#define CS_HT   ((long)NNZ_HHT + NNZ_H)
#define CS_HTH  ((long)NNZ_HHT + NNZ_H + NNZ_HT)

__device__ __align__(16) float g_fs[FS_TOT];
__device__ __align__(16) int   g_is[IS_TOT];

__device__ __forceinline__ float leaky(float v) {
    return v >= 0.f ? v : NEG_SLOPE * v;
}

// ---------------- zero ints ----------------
__global__ void zero_i(int* __restrict__ p, int n) {
    int i = blockIdx.x * blockDim.x + threadIdx.x;
    if (i < n) p[i] = 0;
}

// ---------------- CSR build: count ----------------
__global__ void count_k(const int* __restrict__ rows, int nnz, int* __restrict__ cnt) {
    int i = blockIdx.x * blockDim.x + threadIdx.x;
    if (i < nnz) atomicAdd(&cnt[rows[i]], 1);
}

// ---------------- CSR build: scan (one block per matrix) ----------------
__global__ void scan_all_k(int* __restrict__ cur, int* __restrict__ rp) {
    __shared__ int sh[1024];
    __shared__ int carry;
    int b = blockIdx.x;
    int n;
    int* cnt;
    int* rowp;
    if (b == 0)      { n = NROWS; cnt = cur + CUR_HHT; rowp = rp + RP_HHT; }
    else if (b == 1) { n = NROWS; cnt = cur + CUR_H;   rowp = rp + RP_H;   }
    else if (b == 2) { n = MROWS; cnt = cur + CUR_HT;  rowp = rp + RP_HT;  }
    else             { n = MROWS; cnt = cur + CUR_HTH; rowp = rp + RP_HTH; }

    int tid = threadIdx.x;
    if (tid == 0) carry = 0;
    __syncthreads();
    for (int base = 0; base < n; base += 1024) {
        int i = base + tid;
        int v = (i < n) ? cnt[i] : 0;
        sh[tid] = v;
        __syncthreads();
        #pragma unroll
        for (int off = 1; off < 1024; off <<= 1) {
            int t = (tid >= off) ? sh[tid - off] : 0;
            __syncthreads();
            sh[tid] += t;
            __syncthreads();
        }
        int excl = carry + sh[tid] - v;
        if (i < n) { rowp[i] = excl; cnt[i] = excl; }
        __syncthreads();
        if (tid == 1023) carry += sh[1023];
        __syncthreads();
    }
    if (tid == 0) rowp[n] = carry;
}

// ---------------- CSR build: permute ----------------
__global__ void permute_k(const int* __restrict__ rows, const int* __restrict__ cols,
                          const float* __restrict__ vals, int nnz,
                          int* __restrict__ cursor, int* __restrict__ ccol,
                          float* __restrict__ cval) {
    int i = blockIdx.x * blockDim.x + threadIdx.x;
    if (i >= nnz) return;
    int r = rows[i];
    int slot = atomicAdd(&cursor[r], 1);
    ccol[slot] = cols[i];
    cval[slot] = vals[i];
}

// ---------------- dense GEMM:  C[Rows,Ncols] = A @ W,  K = 256, C stored fp16 ----------------
__global__ void gemm_k256_h(const float* __restrict__ A, const float* __restrict__ W,
                            __half* __restrict__ C, int Rows, int Ncols) {
    const int BM = 64, BN = 64, BK = 16;
    __shared__ __align__(16) float As[BM][BK + 1];
    __shared__ __align__(16) float Ws[BK][BN];

    int tid = threadIdx.x;
    int tx = tid & 15;
    int ty = tid >> 4;
    int m0 = blockIdx.y * BM;
    int n0 = blockIdx.x * BN;

    float acc[4][4] = {};

    for (int k0 = 0; k0 < 256; k0 += BK) {
        {
            int m  = tid >> 2;
            int kq = tid & 3;
            int gm = m0 + m;
            float4 a = make_float4(0.f, 0.f, 0.f, 0.f);
            if (gm < Rows)
                a = *(const float4*)(A + (long)gm * 256 + k0 + kq * 4);
            As[m][kq * 4 + 0] = a.x;
            As[m][kq * 4 + 1] = a.y;
            As[m][kq * 4 + 2] = a.z;
            As[m][kq * 4 + 3] = a.w;
        }
        {
            int k  = tid >> 4;
            int nq = tid & 15;
            float4 w = *(const float4*)(W + (long)(k0 + k) * Ncols + n0 + nq * 4);
            *(float4*)&Ws[k][nq * 4] = w;
        }
        __syncthreads();

        #pragma unroll
        for (int k = 0; k < BK; k++) {
            float ra0 = As[ty * 4 + 0][k];
            float ra1 = As[ty * 4 + 1][k];
            float ra2 = As[ty * 4 + 2][k];
            float ra3 = As[ty * 4 + 3][k];
            float4 rb = *(float4*)&Ws[k][tx * 4];
            acc[0][0] += ra0 * rb.x; acc[0][1] += ra0 * rb.y; acc[0][2] += ra0 * rb.z; acc[0][3] += ra0 * rb.w;
            acc[1][0] += ra1 * rb.x; acc[1][1] += ra1 * rb.y; acc[1][2] += ra1 * rb.z; acc[1][3] += ra1 * rb.w;
            acc[2][0] += ra2 * rb.x; acc[2][1] += ra2 * rb.y; acc[2][2] += ra2 * rb.z; acc[2][3] += ra2 * rb.w;
            acc[3][0] += ra3 * rb.x; acc[3][1] += ra3 * rb.y; acc[3][2] += ra3 * rb.z; acc[3][3] += ra3 * rb.w;
        }
        __syncthreads();
    }

    #pragma unroll
    for (int i = 0; i < 4; i++) {
        int gm = m0 + ty * 4 + i;
        if (gm < Rows) {
            __half2 h0 = __floats2half2_rn(acc[i][0], acc[i][1]);
            __half2 h1 = __floats2half2_rn(acc[i][2], acc[i][3]);
            uint2 u;
            u.x = *(unsigned*)&h0;
            u.y = *(unsigned*)&h1;
            *(uint2*)(C + (long)gm * Ncols + n0 + tx * 4) = u;
        }
    }
}

// ---------------- fused dual CSR SpMM + leaky, F=256, half gather ----------------
// Each lane handles 8 consecutive features (16 bytes of half data).
__device__ __forceinline__ void csr_row_accum_f256h(
    const int* __restrict__ col, const float* __restrict__ val,
    int s, int e, const __half* __restrict__ dense, int lane,
    float* acc)   // acc[8]
{
    if (s >= e) return;
    int c_next = __ldg(col + s);
    float v_next = __ldg(val + s);
    for (int j = s; j < e; j++) {
        int c = c_next;
        float v = v_next;
        if (j + 1 < e) {
            c_next = __ldg(col + j + 1);
            v_next = __ldg(val + j + 1);
        }
        float4 raw = ((const float4*)(dense + (long)c * 256))[lane];
        const __half2* h = (const __half2*)&raw;
        #pragma unroll
        for (int q = 0; q < 4; q++) {
            float2 f = __half22float2(h[q]);
            acc[q * 2 + 0] += v * f.x;
            acc[q * 2 + 1] += v * f.y;
        }
    }
}

__global__ void spmm2_f256h(const int* __restrict__ rpA, const int* __restrict__ colA,
                            const float* __restrict__ valA, const __half* __restrict__ dA,
                            const int* __restrict__ rpB, const int* __restrict__ colB,
                            const float* __restrict__ valB, const __half* __restrict__ dB,
                            float* __restrict__ outp, int nrows) {
    int w = (blockIdx.x * blockDim.x + threadIdx.x) >> 5;
    if (w >= nrows) return;
    int lane = threadIdx.x & 31;

    float a[8] = {}, b[8] = {};

    csr_row_accum_f256h(colA, valA, rpA[w], rpA[w + 1], dA, lane, a);
    csr_row_accum_f256h(colB, valB, rpB[w], rpB[w + 1], dB, lane, b);

    float4 r0, r1;
    r0.x = leaky(a[0]) + leaky(b[0]); r0.y = leaky(a[1]) + leaky(b[1]);
    r0.z = leaky(a[2]) + leaky(b[2]); r0.w = leaky(a[3]) + leaky(b[3]);
    r1.x = leaky(a[4]) + leaky(b[4]); r1.y = leaky(a[5]) + leaky(b[5]);
    r1.z = leaky(a[6]) + leaky(b[6]); r1.w = leaky(a[7]) + leaky(b[7]);
    float4* dst = (float4*)(outp + (long)w * 256) + lane * 2;
    dst[0] = r0;
    dst[1] = r1;
}

// ---------------- fused dual CSR SpMM + leaky, F=64, half gather ----------------
// Each lane handles 2 consecutive features (one half2 = 4 bytes).
__global__ void spmm2_f64h(const int* __restrict__ rpA, const int* __restrict__ colA,
                           const float* __restrict__ valA, const __half* __restrict__ dA,
                           const int* __restrict__ rpB, const int* __restrict__ colB,
                           const float* __restrict__ valB, const __half* __restrict__ dB,
                           float* __restrict__ outp, int nrows) {
    int w = (blockIdx.x * blockDim.x + threadIdx.x) >> 5;
    if (w >= nrows) return;
    int lane = threadIdx.x & 31;

    float2 a = make_float2(0, 0), b = a;

    int s = rpA[w], e = rpA[w + 1];
    for (int j = s; j < e; j++) {
        int c = __ldg(colA + j);
        float v = __ldg(valA + j);
        __half2 hraw = ((const __half2*)(dA + (long)c * 64))[lane];
        float2 d = __half22float2(hraw);
        a.x += v * d.x; a.y += v * d.y;
    }
    s = rpB[w]; e = rpB[w + 1];
    for (int j = s; j < e; j++) {
        int c = __ldg(colB + j);
        float v = __ldg(valB + j);
        __half2 hraw = ((const __half2*)(dB + (long)c * 64))[lane];
        float2 d = __half22float2(hraw);
        b.x += v * d.x; b.y += v * d.y;
    }

    float2 r;
    r.x = leaky(a.x) + leaky(b.x);
    r.y = leaky(a.y) + leaky(b.y);
    ((float2*)(outp + (long)w * 64))[lane] = r;
}

extern "C" void kernel_launch(void* const* d_in, const int* in_sizes, int n_in,
                              void* d_out, int out_size) {
    const float* x  = (const float*)d_in[0];
    const float* y  = (const float*)d_in[1];
    const float* W0 = (const float*)d_in[2];
    const float* W1 = (const float*)d_in[3];
    const int*   hht_r = (const int*)d_in[4];
    const int*   hht_c = (const int*)d_in[5];
    const float* hht_v = (const float*)d_in[6];
    const int*   h_r = (const int*)d_in[7];
    const int*   h_c = (const int*)d_in[8];
    const float* h_v = (const float*)d_in[9];
    const int*   ht_r = (const int*)d_in[10];
    const int*   ht_c = (const int*)d_in[11];
    const float* ht_v = (const float*)d_in[12];
    const int*   hth_r = (const int*)d_in[13];
    const int*   hth_c = (const int*)d_in[14];
    const float* hth_v = (const float*)d_in[15];
    float* out = (float*)d_out;

    void* p = nullptr;
    cudaGetSymbolAddress(&p, g_fs);
    float* F = (float*)p;
    cudaGetSymbolAddress(&p, g_is);
    int* I = (int*)p;

    __half* xw0  = (__half*)(F + O_XW0);
    __half* yw0  = (__half*)(F + O_YW0);
    float*  x1   = F + O_X1;
    float*  y1   = F + O_Y1;
    __half* x1w1 = (__half*)(F + O_X1W1);
    __half* y1w1 = (__half*)(F + O_Y1W1);
    float*  cval = F + O_CVAL;

    int* cur  = I + I_CUR;
    int* rp   = I + I_RP;
    int* ccol = I + I_CCOL;

    const int T = 256;

    // ---- CSR build ----
    {
        int ncur = 2 * NROWS + 2 * MROWS;
        zero_i<<<(ncur + T - 1) / T, T>>>(cur, ncur);

        count_k<<<(NNZ_HHT + T - 1) / T, T>>>(hht_r, NNZ_HHT, cur + CUR_HHT);
        count_k<<<(NNZ_H   + T - 1) / T, T>>>(h_r,   NNZ_H,   cur + CUR_H);
        count_k<<<(NNZ_HT  + T - 1) / T, T>>>(ht_r,  NNZ_HT,  cur + CUR_HT);
        count_k<<<(NNZ_HTH + T - 1) / T, T>>>(hth_r, NNZ_HTH, cur + CUR_HTH);

        scan_all_k<<<4, 1024>>>(cur, rp);

        permute_k<<<(NNZ_HHT + T - 1) / T, T>>>(hht_r, hht_c, hht_v, NNZ_HHT,
                                                cur + CUR_HHT, ccol + CS_HHT, cval + CS_HHT);
        permute_k<<<(NNZ_H + T - 1) / T, T>>>(h_r, h_c, h_v, NNZ_H,
                                              cur + CUR_H, ccol + CS_H, cval + CS_H);
        permute_k<<<(NNZ_HT + T - 1) / T, T>>>(ht_r, ht_c, ht_v, NNZ_HT,
                                               cur + CUR_HT, ccol + CS_HT, cval + CS_HT);
        permute_k<<<(NNZ_HTH + T - 1) / T, T>>>(hth_r, hth_c, hth_v, NNZ_HTH,
                                                cur + CUR_HTH, ccol + CS_HTH, cval + CS_HTH);
    }

    // ---- layer-0 dense GEMMs (fp32 compute, fp16 store) ----
    {
        dim3 gx(256 / 64, (NROWS + 63) / 64);
        gemm_k256_h<<<gx, T>>>(x, W0, xw0, NROWS, 256);
        dim3 gy(256 / 64, (MROWS + 63) / 64);
        gemm_k256_h<<<gy, T>>>(y, W0, yw0, MROWS, 256);
    }

    // ---- layer-0 fused SpMM (fp16 gather, fp32 accumulate) ----
    spmm2_f256h<<<(NROWS + 7) / 8, T>>>(rp + RP_HHT, ccol + CS_HHT, cval + CS_HHT, xw0,
                                        rp + RP_H,   ccol + CS_H,   cval + CS_H,   yw0,
                                        x1, NROWS);
    spmm2_f256h<<<(MROWS + 7) / 8, T>>>(rp + RP_HT,  ccol + CS_HT,  cval + CS_HT,  xw0,
                                        rp + RP_HTH, ccol + CS_HTH, cval + CS_HTH, yw0,
                                        y1, MROWS);

    // ---- layer-1 dense GEMMs (fp32 compute, fp16 store) ----
    {
        dim3 gx(64 / 64, (NROWS + 63) / 64);
        gemm_k256_h<<<gx, T>>>(x1, W1, x1w1, NROWS, 64);
        dim3 gy(64 / 64, (MROWS + 63) / 64);
        gemm_k256_h<<<gy, T>>>(y1, W1, y1w1, MROWS, 64);
    }

    // ---- layer-1 fused SpMM straight into d_out ----
    spmm2_f64h<<<(NROWS + 7) / 8, T>>>(rp + RP_HHT, ccol + CS_HHT, cval + CS_HHT, x1w1,
                                       rp + RP_H,   ccol + CS_H,   cval + CS_H,   y1w1,
                                       out, NROWS);
    spmm2_f64h<<<(MROWS + 7) / 8, T>>>(rp + RP_HT,  ccol + CS_HT,  cval + CS_HT,  x1w1,
                                       rp + RP_HTH, ccol + CS_HTH, cval + CS_HTH, y1w1,
                                       out + (long)NROWS * 64, MROWS);
}

// round 5
// speedup vs baseline: 1.8856x; 1.0901x over previous
#include <cuda_runtime.h>
#include <cuda_fp16.h>
#include <cstdint>

// ---------------- problem constants ----------------
#define NROWS 50000
#define MROWS 20000
#define NNZ_HHT 1600000
#define NNZ_H   1000000
#define NNZ_HT  1000000
#define NNZ_HTH 640000
#define NNZ_TOT (NNZ_HHT + NNZ_H + NNZ_HT + NNZ_HTH)
#define NEG_SLOPE 0.2f

// ---------------- float-unit scratch layout ----------------
#define O_XW0   0L                        // [N,256] half
#define O_YW0   (O_XW0  + 6400000L)       // [M,256] half
#define O_X1    (O_YW0  + 2560000L)       // [N,256] float
#define O_Y1    (O_X1   + 12800000L)      // [M,256] float
#define O_X1W1  (O_Y1   + 5120000L)       // [N,64] half
#define O_Y1W1  (O_X1W1 + 1600000L)       // [M,64] half
#define O_CVAL  (O_Y1W1 + 640000L)        // [NNZ_TOT] float
#define FS_TOT  (O_CVAL + (long)NNZ_TOT)

// ---------------- int scratch layout ----------------
#define I_CUR   0L
#define I_RP    (I_CUR + 2L*NROWS + 2L*MROWS)
#define I_CCOL  (I_RP  + 2L*(NROWS+1) + 2L*(MROWS+1))
#define IS_TOT  (I_CCOL + (long)NNZ_TOT)

#define CUR_HHT 0L
#define CUR_H   ((long)NROWS)
#define CUR_HT  (2L*NROWS)
#define CUR_HTH (2L*NROWS + MROWS)
#define RP_HHT  0L
#define RP_H    ((long)NROWS + 1)
#define RP_HT   (2L*(NROWS + 1))
#define RP_HTH  (2L*(NROWS + 1) + MROWS + 1)
#define CS_HHT  0L
#define CS_H    ((long)NNZ_HHT)
#define CS_HT   ((long)NNZ_HHT + NNZ_H)
#define CS_HTH  ((long)NNZ_HHT + NNZ_H + NNZ_HT)

__device__ __align__(16) float g_fs[FS_TOT];
__device__ __align__(16) int   g_is[IS_TOT];

__device__ __forceinline__ float leaky(float v) {
    return v >= 0.f ? v : NEG_SLOPE * v;
}

// ---------------- zero ints ----------------
__global__ void zero_i(int* __restrict__ p, int n) {
    int i = blockIdx.x * blockDim.x + threadIdx.x;
    if (i < n) p[i] = 0;
}

// ---------------- CSR build: count all 4 matrices in one launch ----------------
__global__ void count_all_k(const int* __restrict__ r0, const int* __restrict__ r1,
                            const int* __restrict__ r2, const int* __restrict__ r3,
                            int* __restrict__ cur) {
    long i = (long)blockIdx.x * blockDim.x + threadIdx.x;
    if (i >= NNZ_TOT) return;
    if (i < NNZ_HHT) {
        atomicAdd(&cur[CUR_HHT + r0[i]], 1);
    } else if (i < NNZ_HHT + NNZ_H) {
        atomicAdd(&cur[CUR_H + r1[i - NNZ_HHT]], 1);
    } else if (i < NNZ_HHT + NNZ_H + NNZ_HT) {
        atomicAdd(&cur[CUR_HT + r2[i - NNZ_HHT - NNZ_H]], 1);
    } else {
        atomicAdd(&cur[CUR_HTH + r3[i - NNZ_HHT - NNZ_H - NNZ_HT]], 1);
    }
}

// ---------------- CSR build: scan (one block per matrix) ----------------
__global__ void scan_all_k(int* __restrict__ cur, int* __restrict__ rp) {
    __shared__ int sh[1024];
    __shared__ int carry;
    int b = blockIdx.x;
    int n;
    int* cnt;
    int* rowp;
    if (b == 0)      { n = NROWS; cnt = cur + CUR_HHT; rowp = rp + RP_HHT; }
    else if (b == 1) { n = NROWS; cnt = cur + CUR_H;   rowp = rp + RP_H;   }
    else if (b == 2) { n = MROWS; cnt = cur + CUR_HT;  rowp = rp + RP_HT;  }
    else             { n = MROWS; cnt = cur + CUR_HTH; rowp = rp + RP_HTH; }

    int tid = threadIdx.x;
    if (tid == 0) carry = 0;
    __syncthreads();
    for (int base = 0; base < n; base += 1024) {
        int i = base + tid;
        int v = (i < n) ? cnt[i] : 0;
        sh[tid] = v;
        __syncthreads();
        #pragma unroll
        for (int off = 1; off < 1024; off <<= 1) {
            int t = (tid >= off) ? sh[tid - off] : 0;
            __syncthreads();
            sh[tid] += t;
            __syncthreads();
        }
        int excl = carry + sh[tid] - v;
        if (i < n) { rowp[i] = excl; cnt[i] = excl; }
        __syncthreads();
        if (tid == 1023) carry += sh[1023];
        __syncthreads();
    }
    if (tid == 0) rowp[n] = carry;
}

// ---------------- CSR build: permute all 4 matrices in one launch ----------------
__global__ void permute_all_k(const int* __restrict__ r0, const int* __restrict__ c0, const float* __restrict__ v0,
                              const int* __restrict__ r1, const int* __restrict__ c1, const float* __restrict__ v1,
                              const int* __restrict__ r2, const int* __restrict__ c2, const float* __restrict__ v2,
                              const int* __restrict__ r3, const int* __restrict__ c3, const float* __restrict__ v3,
                              int* __restrict__ cur, int* __restrict__ ccol, float* __restrict__ cval) {
    long i = (long)blockIdx.x * blockDim.x + threadIdx.x;
    if (i >= NNZ_TOT) return;
    int r, c; float v; long cs; int* cu;
    if (i < NNZ_HHT) {
        r = r0[i]; c = c0[i]; v = v0[i]; cs = CS_HHT; cu = cur + CUR_HHT;
    } else if (i < NNZ_HHT + NNZ_H) {
        long j = i - NNZ_HHT;
        r = r1[j]; c = c1[j]; v = v1[j]; cs = CS_H; cu = cur + CUR_H;
    } else if (i < NNZ_HHT + NNZ_H + NNZ_HT) {
        long j = i - NNZ_HHT - NNZ_H;
        r = r2[j]; c = c2[j]; v = v2[j]; cs = CS_HT; cu = cur + CUR_HT;
    } else {
        long j = i - NNZ_HHT - NNZ_H - NNZ_HT;
        r = r3[j]; c = c3[j]; v = v3[j]; cs = CS_HTH; cu = cur + CUR_HTH;
    }
    int slot = atomicAdd(&cu[r], 1);
    ccol[cs + slot] = c;
    cval[cs + slot] = v;
}

// ---------------- combined dense GEMM: two matrices, K = 256, C stored fp16 ----------------
__global__ void gemm2_k256_h(const float* __restrict__ A1, int Rows1,
                             const float* __restrict__ A2, int Rows2,
                             const float* __restrict__ W,
                             __half* __restrict__ C1, __half* __restrict__ C2,
                             int Ncols, int nb1) {
    const int BM = 64, BN = 64, BK = 16;
    __shared__ __align__(16) float As[BM][BK + 1];
    __shared__ __align__(16) float Ws[BK][BN];

    const float* A;
    __half* C;
    int Rows, m0;
    if ((int)blockIdx.y < nb1) { A = A1; C = C1; Rows = Rows1; m0 = blockIdx.y * BM; }
    else                        { A = A2; C = C2; Rows = Rows2; m0 = (blockIdx.y - nb1) * BM; }

    int tid = threadIdx.x;
    int tx = tid & 15;
    int ty = tid >> 4;
    int n0 = blockIdx.x * BN;

    float acc[4][4] = {};

    for (int k0 = 0; k0 < 256; k0 += BK) {
        {
            int m  = tid >> 2;
            int kq = tid & 3;
            int gm = m0 + m;
            float4 a = make_float4(0.f, 0.f, 0.f, 0.f);
            if (gm < Rows)
                a = *(const float4*)(A + (long)gm * 256 + k0 + kq * 4);
            As[m][kq * 4 + 0] = a.x;
            As[m][kq * 4 + 1] = a.y;
            As[m][kq * 4 + 2] = a.z;
            As[m][kq * 4 + 3] = a.w;
        }
        {
            int k  = tid >> 4;
            int nq = tid & 15;
            float4 w = *(const float4*)(W + (long)(k0 + k) * Ncols + n0 + nq * 4);
            *(float4*)&Ws[k][nq * 4] = w;
        }
        __syncthreads();

        #pragma unroll
        for (int k = 0; k < BK; k++) {
            float ra0 = As[ty * 4 + 0][k];
            float ra1 = As[ty * 4 + 1][k];
            float ra2 = As[ty * 4 + 2][k];
            float ra3 = As[ty * 4 + 3][k];
            float4 rb = *(float4*)&Ws[k][tx * 4];
            acc[0][0] += ra0 * rb.x; acc[0][1] += ra0 * rb.y; acc[0][2] += ra0 * rb.z; acc[0][3] += ra0 * rb.w;
            acc[1][0] += ra1 * rb.x; acc[1][1] += ra1 * rb.y; acc[1][2] += ra1 * rb.z; acc[1][3] += ra1 * rb.w;
            acc[2][0] += ra2 * rb.x; acc[2][1] += ra2 * rb.y; acc[2][2] += ra2 * rb.z; acc[2][3] += ra2 * rb.w;
            acc[3][0] += ra3 * rb.x; acc[3][1] += ra3 * rb.y; acc[3][2] += ra3 * rb.z; acc[3][3] += ra3 * rb.w;
        }
        __syncthreads();
    }

    #pragma unroll
    for (int i = 0; i < 4; i++) {
        int gm = m0 + ty * 4 + i;
        if (gm < Rows) {
            __half2 h0 = __floats2half2_rn(acc[i][0], acc[i][1]);
            __half2 h1 = __floats2half2_rn(acc[i][2], acc[i][3]);
            uint2 u;
            u.x = *(unsigned*)&h0;
            u.y = *(unsigned*)&h1;
            *(uint2*)(C + (long)gm * Ncols + n0 + tx * 4) = u;
        }
    }
}

// ---------------- F=256 gather accumulate, MLP=4 pipelined ----------------
__device__ __forceinline__ void macc8(float* acc, float4 raw, float v) {
    const __half2* h = (const __half2*)&raw;
    #pragma unroll
    for (int q = 0; q < 4; q++) {
        float2 f = __half22float2(h[q]);
        acc[q * 2 + 0] += v * f.x;
        acc[q * 2 + 1] += v * f.y;
    }
}

__device__ __forceinline__ void accum256(const int* __restrict__ col, const float* __restrict__ val,
                                         int s, int e, const __half* __restrict__ dense,
                                         int lane, float* acc) {
    int j = s;
    if (j + 4 <= e) {
        int   c0 = __ldg(col + j),     c1 = __ldg(col + j + 1);
        int   c2 = __ldg(col + j + 2), c3 = __ldg(col + j + 3);
        float v0 = __ldg(val + j),     v1 = __ldg(val + j + 1);
        float v2 = __ldg(val + j + 2), v3 = __ldg(val + j + 3);
        for (; j + 4 <= e; ) {
            // issue 4 independent dense gathers
            float4 r0 = ((const float4*)(dense + (long)c0 * 256))[lane];
            float4 r1 = ((const float4*)(dense + (long)c1 * 256))[lane];
            float4 r2 = ((const float4*)(dense + (long)c2 * 256))[lane];
            float4 r3 = ((const float4*)(dense + (long)c3 * 256))[lane];
            float w0 = v0, w1 = v1, w2 = v2, w3 = v3;
            j += 4;
            // prefetch next block's indices while gathers are in flight
            if (j + 4 <= e) {
                c0 = __ldg(col + j);     c1 = __ldg(col + j + 1);
                c2 = __ldg(col + j + 2); c3 = __ldg(col + j + 3);
                v0 = __ldg(val + j);     v1 = __ldg(val + j + 1);
                v2 = __ldg(val + j + 2); v3 = __ldg(val + j + 3);
            }
            macc8(acc, r0, w0);
            macc8(acc, r1, w1);
            macc8(acc, r2, w2);
            macc8(acc, r3, w3);
        }
    }
    for (; j < e; j++) {
        int c = __ldg(col + j);
        float v = __ldg(val + j);
        float4 r = ((const float4*)(dense + (long)c * 256))[lane];
        macc8(acc, r, v);
    }
}

// ---------------- combined F=256 dual SpMM + leaky: x1 and y1 in one launch ----------------
__global__ void spmm256_all(const int* __restrict__ rp, const int* __restrict__ ccol,
                            const float* __restrict__ cval,
                            const __half* __restrict__ dX, const __half* __restrict__ dY,
                            float* __restrict__ x1, float* __restrict__ y1) {
    int w = (blockIdx.x * blockDim.x + threadIdx.x) >> 5;
    if (w >= NROWS + MROWS) return;
    int lane = threadIdx.x & 31;

    const int* rpA; const int* rpB; long csA, csB; float* outp; int r;
    if (w < NROWS) {
        r = w;
        rpA = rp + RP_HHT; csA = CS_HHT;
        rpB = rp + RP_H;   csB = CS_H;
        outp = x1;
    } else {
        r = w - NROWS;
        rpA = rp + RP_HT;  csA = CS_HT;
        rpB = rp + RP_HTH; csB = CS_HTH;
        outp = y1;
    }

    float a[8] = {}, b[8] = {};
    accum256(ccol + csA, cval + csA, rpA[r], rpA[r + 1], dX, lane, a);
    accum256(ccol + csB, cval + csB, rpB[r], rpB[r + 1], dY, lane, b);

    float4 r0, r1;
    r0.x = leaky(a[0]) + leaky(b[0]); r0.y = leaky(a[1]) + leaky(b[1]);
    r0.z = leaky(a[2]) + leaky(b[2]); r0.w = leaky(a[3]) + leaky(b[3]);
    r1.x = leaky(a[4]) + leaky(b[4]); r1.y = leaky(a[5]) + leaky(b[5]);
    r1.z = leaky(a[6]) + leaky(b[6]); r1.w = leaky(a[7]) + leaky(b[7]);
    float4* dst = (float4*)(outp + (long)r * 256) + lane * 2;
    dst[0] = r0;
    dst[1] = r1;
}

// ---------------- F=64 gather accumulate, MLP=4 pipelined ----------------
__device__ __forceinline__ void accum64(const int* __restrict__ col, const float* __restrict__ val,
                                        int s, int e, const __half* __restrict__ dense,
                                        int lane, float2& acc) {
    int j = s;
    if (j + 4 <= e) {
        int   c0 = __ldg(col + j),     c1 = __ldg(col + j + 1);
        int   c2 = __ldg(col + j + 2), c3 = __ldg(col + j + 3);
        float v0 = __ldg(val + j),     v1 = __ldg(val + j + 1);
        float v2 = __ldg(val + j + 2), v3 = __ldg(val + j + 3);
        for (; j + 4 <= e; ) {
            __half2 h0 = ((const __half2*)(dense + (long)c0 * 64))[lane];
            __half2 h1 = ((const __half2*)(dense + (long)c1 * 64))[lane];
            __half2 h2 = ((const __half2*)(dense + (long)c2 * 64))[lane];
            __half2 h3 = ((const __half2*)(dense + (long)c3 * 64))[lane];
            float w0 = v0, w1 = v1, w2 = v2, w3 = v3;
            j += 4;
            if (j + 4 <= e) {
                c0 = __ldg(col + j);     c1 = __ldg(col + j + 1);
                c2 = __ldg(col + j + 2); c3 = __ldg(col + j + 3);
                v0 = __ldg(val + j);     v1 = __ldg(val + j + 1);
                v2 = __ldg(val + j + 2); v3 = __ldg(val + j + 3);
            }
            float2 f;
            f = __half22float2(h0); acc.x += w0 * f.x; acc.y += w0 * f.y;
            f = __half22float2(h1); acc.x += w1 * f.x; acc.y += w1 * f.y;
            f = __half22float2(h2); acc.x += w2 * f.x; acc.y += w2 * f.y;
            f = __half22float2(h3); acc.x += w3 * f.x; acc.y += w3 * f.y;
        }
    }
    for (; j < e; j++) {
        int c = __ldg(col + j);
        float v = __ldg(val + j);
        float2 f = __half22float2(((const __half2*)(dense + (long)c * 64))[lane]);
        acc.x += v * f.x; acc.y += v * f.y;
    }
}

// ---------------- combined F=64 dual SpMM + leaky straight into d_out ----------------
__global__ void spmm64_all(const int* __restrict__ rp, const int* __restrict__ ccol,
                           const float* __restrict__ cval,
                           const __half* __restrict__ dX, const __half* __restrict__ dY,
                           float* __restrict__ outbase) {
    int w = (blockIdx.x * blockDim.x + threadIdx.x) >> 5;
    if (w >= NROWS + MROWS) return;
    int lane = threadIdx.x & 31;

    const int* rpA; const int* rpB; long csA, csB; int r;
    if (w < NROWS) {
        r = w;
        rpA = rp + RP_HHT; csA = CS_HHT;
        rpB = rp + RP_H;   csB = CS_H;
    } else {
        r = w - NROWS;
        rpA = rp + RP_HT;  csA = CS_HT;
        rpB = rp + RP_HTH; csB = CS_HTH;
    }

    float2 a = make_float2(0, 0), b = a;
    accum64(ccol + csA, cval + csA, rpA[r], rpA[r + 1], dX, lane, a);
    accum64(ccol + csB, cval + csB, rpB[r], rpB[r + 1], dY, lane, b);

    float2 res;
    res.x = leaky(a.x) + leaky(b.x);
    res.y = leaky(a.y) + leaky(b.y);
    ((float2*)(outbase + (long)w * 64))[lane] = res;
}

extern "C" void kernel_launch(void* const* d_in, const int* in_sizes, int n_in,
                              void* d_out, int out_size) {
    const float* x  = (const float*)d_in[0];
    const float* y  = (const float*)d_in[1];
    const float* W0 = (const float*)d_in[2];
    const float* W1 = (const float*)d_in[3];
    const int*   hht_r = (const int*)d_in[4];
    const int*   hht_c = (const int*)d_in[5];
    const float* hht_v = (const float*)d_in[6];
    const int*   h_r = (const int*)d_in[7];
    const int*   h_c = (const int*)d_in[8];
    const float* h_v = (const float*)d_in[9];
    const int*   ht_r = (const int*)d_in[10];
    const int*   ht_c = (const int*)d_in[11];
    const float* ht_v = (const float*)d_in[12];
    const int*   hth_r = (const int*)d_in[13];
    const int*   hth_c = (const int*)d_in[14];
    const float* hth_v = (const float*)d_in[15];
    float* out = (float*)d_out;

    void* p = nullptr;
    cudaGetSymbolAddress(&p, g_fs);
    float* F = (float*)p;
    cudaGetSymbolAddress(&p, g_is);
    int* I = (int*)p;

    __half* xw0  = (__half*)(F + O_XW0);
    __half* yw0  = (__half*)(F + O_YW0);
    float*  x1   = F + O_X1;
    float*  y1   = F + O_Y1;
    __half* x1w1 = (__half*)(F + O_X1W1);
    __half* y1w1 = (__half*)(F + O_Y1W1);
    float*  cval = F + O_CVAL;

    int* cur  = I + I_CUR;
    int* rp   = I + I_RP;
    int* ccol = I + I_CCOL;

    const int T = 256;

    // launch 1: zero counters
    {
        int ncur = 2 * NROWS + 2 * MROWS;
        zero_i<<<(ncur + T - 1) / T, T>>>(cur, ncur);
    }
    // launch 2: count all
    count_all_k<<<(NNZ_TOT + T - 1) / T, T>>>(hht_r, h_r, ht_r, hth_r, cur);
    // launch 3: scan
    scan_all_k<<<4, 1024>>>(cur, rp);
    // launch 4: permute all
    permute_all_k<<<(NNZ_TOT + T - 1) / T, T>>>(hht_r, hht_c, hht_v,
                                                h_r, h_c, h_v,
                                                ht_r, ht_c, ht_v,
                                                hth_r, hth_c, hth_v,
                                                cur, ccol, cval);
    // launch 5: layer-0 GEMMs (combined)
    {
        int nb1 = (NROWS + 63) / 64, nb2 = (MROWS + 63) / 64;
        dim3 g(256 / 64, nb1 + nb2);
        gemm2_k256_h<<<g, T>>>(x, NROWS, y, MROWS, W0, xw0, yw0, 256, nb1);
    }
    // launch 6: layer-0 SpMM (combined, profiled by ncu slot)
    spmm256_all<<<(NROWS + MROWS + 7) / 8, T>>>(rp, ccol, cval, xw0, yw0, x1, y1);
    // launch 7: layer-1 GEMMs (combined)
    {
        int nb1 = (NROWS + 63) / 64, nb2 = (MROWS + 63) / 64;
        dim3 g(64 / 64, nb1 + nb2);
        gemm2_k256_h<<<g, T>>>(x1, NROWS, y1, MROWS, W1, x1w1, y1w1, 64, nb1);
    }
    // launch 8: layer-1 SpMM (combined) straight into d_out
    spmm64_all<<<(NROWS + MROWS + 7) / 8, T>>>(rp, ccol, cval, x1w1, y1w1, out);
}

// round 6
// speedup vs baseline: 1.9094x; 1.0126x over previous
#include <cuda_runtime.h>
#include <cuda_fp16.h>
#include <cstdint>

// ---------------- problem constants ----------------
#define NROWS 50000
#define MROWS 20000
#define NNZ_HHT 1600000
#define NNZ_H   1000000
#define NNZ_HT  1000000
#define NNZ_HTH 640000
#define NNZ_TOT (NNZ_HHT + NNZ_H + NNZ_HT + NNZ_HTH)
#define NEG_SLOPE 0.2f

// ---------------- half scratch (element counts) ----------------
// xw0  [N,256], yw0 [M,256], x1h [N,256], y1h [M,256], x1w1 [N,64], y1w1 [M,64]
#define H_XW0   0L
#define H_YW0   (H_XW0  + 12800000L)
#define H_X1    (H_YW0  + 5120000L)
#define H_Y1    (H_X1   + 12800000L)
#define H_X1W1  (H_Y1   + 5120000L)
#define H_Y1W1  (H_X1W1 + 3200000L)
#define HS_TOT  (H_Y1W1 + 1280000L)

// ---------------- int scratch ----------------
#define I_CUR   0L
#define I_RP    (I_CUR + 2L*NROWS + 2L*MROWS)
#define IS_TOT  (I_RP  + 2L*(NROWS+1) + 2L*(MROWS+1))

#define CUR_HHT 0L
#define CUR_H   ((long)NROWS)
#define CUR_HT  (2L*NROWS)
#define CUR_HTH (2L*NROWS + MROWS)
#define RP_HHT  0L
#define RP_H    ((long)NROWS + 1)
#define RP_HT   (2L*(NROWS + 1))
#define RP_HTH  (2L*(NROWS + 1) + MROWS + 1)
#define CS_HHT  0L
#define CS_H    ((long)NNZ_HHT)
#define CS_HT   ((long)NNZ_HHT + NNZ_H)
#define CS_HTH  ((long)NNZ_HHT + NNZ_H + NNZ_HT)

__device__ __align__(16) __half g_hs[HS_TOT];
__device__ __align__(16) int    g_is[IS_TOT];
__device__ __align__(16) int2   g_pack[NNZ_TOT];   // packed (col, val-bits)

__device__ __forceinline__ float leaky(float v) {
    return v >= 0.f ? v : NEG_SLOPE * v;
}

// ---------------- zero ints ----------------
__global__ void zero_i(int* __restrict__ p, int n) {
    int i = blockIdx.x * blockDim.x + threadIdx.x;
    if (i < n) p[i] = 0;
}

// ---------------- CSR build: count all 4 matrices in one launch ----------------
__global__ void count_all_k(const int* __restrict__ r0, const int* __restrict__ r1,
                            const int* __restrict__ r2, const int* __restrict__ r3,
                            int* __restrict__ cur) {
    long i = (long)blockIdx.x * blockDim.x + threadIdx.x;
    if (i >= NNZ_TOT) return;
    if (i < NNZ_HHT) {
        atomicAdd(&cur[CUR_HHT + r0[i]], 1);
    } else if (i < NNZ_HHT + NNZ_H) {
        atomicAdd(&cur[CUR_H + r1[i - NNZ_HHT]], 1);
    } else if (i < NNZ_HHT + NNZ_H + NNZ_HT) {
        atomicAdd(&cur[CUR_HT + r2[i - NNZ_HHT - NNZ_H]], 1);
    } else {
        atomicAdd(&cur[CUR_HTH + r3[i - NNZ_HHT - NNZ_H - NNZ_HT]], 1);
    }
}

// ---------------- CSR build: scan (one block per matrix) ----------------
__global__ void scan_all_k(int* __restrict__ cur, int* __restrict__ rp) {
    __shared__ int sh[1024];
    __shared__ int carry;
    int b = blockIdx.x;
    int n;
    int* cnt;
    int* rowp;
    if (b == 0)      { n = NROWS; cnt = cur + CUR_HHT; rowp = rp + RP_HHT; }
    else if (b == 1) { n = NROWS; cnt = cur + CUR_H;   rowp = rp + RP_H;   }
    else if (b == 2) { n = MROWS; cnt = cur + CUR_HT;  rowp = rp + RP_HT;  }
    else             { n = MROWS; cnt = cur + CUR_HTH; rowp = rp + RP_HTH; }

    int tid = threadIdx.x;
    if (tid == 0) carry = 0;
    __syncthreads();
    for (int base = 0; base < n; base += 1024) {
        int i = base + tid;
        int v = (i < n) ? cnt[i] : 0;
        sh[tid] = v;
        __syncthreads();
        #pragma unroll
        for (int off = 1; off < 1024; off <<= 1) {
            int t = (tid >= off) ? sh[tid - off] : 0;
            __syncthreads();
            sh[tid] += t;
            __syncthreads();
        }
        int excl = carry + sh[tid] - v;
        if (i < n) { rowp[i] = excl; cnt[i] = excl; }
        __syncthreads();
        if (tid == 1023) carry += sh[1023];
        __syncthreads();
    }
    if (tid == 0) rowp[n] = carry;
}

// ---------------- CSR build: permute all, packed 8B entries ----------------
__global__ void permute_all_k(const int* __restrict__ r0, const int* __restrict__ c0, const float* __restrict__ v0,
                              const int* __restrict__ r1, const int* __restrict__ c1, const float* __restrict__ v1,
                              const int* __restrict__ r2, const int* __restrict__ c2, const float* __restrict__ v2,
                              const int* __restrict__ r3, const int* __restrict__ c3, const float* __restrict__ v3,
                              int* __restrict__ cur, int2* __restrict__ pack) {
    long i = (long)blockIdx.x * blockDim.x + threadIdx.x;
    if (i >= NNZ_TOT) return;
    int r, c; float v; long cs; int* cu;
    if (i < NNZ_HHT) {
        r = r0[i]; c = c0[i]; v = v0[i]; cs = CS_HHT; cu = cur + CUR_HHT;
    } else if (i < NNZ_HHT + NNZ_H) {
        long j = i - NNZ_HHT;
        r = r1[j]; c = c1[j]; v = v1[j]; cs = CS_H; cu = cur + CUR_H;
    } else if (i < NNZ_HHT + NNZ_H + NNZ_HT) {
        long j = i - NNZ_HHT - NNZ_H;
        r = r2[j]; c = c2[j]; v = v2[j]; cs = CS_HT; cu = cur + CUR_HT;
    } else {
        long j = i - NNZ_HHT - NNZ_H - NNZ_HT;
        r = r3[j]; c = c3[j]; v = v3[j]; cs = CS_HTH; cu = cur + CUR_HTH;
    }
    int slot = atomicAdd(&cu[r], 1);
    pack[cs + slot] = make_int2(c, __float_as_int(v));
}

// ---------------- combined dense GEMM, K=256, C fp16; A fp32 or fp16 ----------------
template<int AHALF>
__global__ void gemm2_k256(const void* __restrict__ A1v, int Rows1,
                           const void* __restrict__ A2v, int Rows2,
                           const float* __restrict__ W,
                           __half* __restrict__ C1, __half* __restrict__ C2,
                           int Ncols, int nb1) {
    const int BM = 64, BN = 64, BK = 16;
    __shared__ __align__(16) float As[BM][BK + 1];
    __shared__ __align__(16) float Ws[BK][BN];

    const void* Av;
    __half* C;
    int Rows, m0;
    if ((int)blockIdx.y < nb1) { Av = A1v; C = C1; Rows = Rows1; m0 = blockIdx.y * BM; }
    else                        { Av = A2v; C = C2; Rows = Rows2; m0 = (blockIdx.y - nb1) * BM; }

    int tid = threadIdx.x;
    int tx = tid & 15;
    int ty = tid >> 4;
    int n0 = blockIdx.x * BN;

    float acc[4][4] = {};

    for (int k0 = 0; k0 < 256; k0 += BK) {
        {
            int m  = tid >> 2;
            int kq = tid & 3;
            int gm = m0 + m;
            float4 a = make_float4(0.f, 0.f, 0.f, 0.f);
            if (gm < Rows) {
                if (AHALF) {
                    const __half* A = (const __half*)Av;
                    uint2 u = *(const uint2*)(A + (long)gm * 256 + k0 + kq * 4);
                    float2 f0 = __half22float2(*(__half2*)&u.x);
                    float2 f1 = __half22float2(*(__half2*)&u.y);
                    a = make_float4(f0.x, f0.y, f1.x, f1.y);
                } else {
                    const float* A = (const float*)Av;
                    a = *(const float4*)(A + (long)gm * 256 + k0 + kq * 4);
                }
            }
            As[m][kq * 4 + 0] = a.x;
            As[m][kq * 4 + 1] = a.y;
            As[m][kq * 4 + 2] = a.z;
            As[m][kq * 4 + 3] = a.w;
        }
        {
            int k  = tid >> 4;
            int nq = tid & 15;
            float4 w = *(const float4*)(W + (long)(k0 + k) * Ncols + n0 + nq * 4);
            *(float4*)&Ws[k][nq * 4] = w;
        }
        __syncthreads();

        #pragma unroll
        for (int k = 0; k < BK; k++) {
            float ra0 = As[ty * 4 + 0][k];
            float ra1 = As[ty * 4 + 1][k];
            float ra2 = As[ty * 4 + 2][k];
            float ra3 = As[ty * 4 + 3][k];
            float4 rb = *(float4*)&Ws[k][tx * 4];
            acc[0][0] += ra0 * rb.x; acc[0][1] += ra0 * rb.y; acc[0][2] += ra0 * rb.z; acc[0][3] += ra0 * rb.w;
            acc[1][0] += ra1 * rb.x; acc[1][1] += ra1 * rb.y; acc[1][2] += ra1 * rb.z; acc[1][3] += ra1 * rb.w;
            acc[2][0] += ra2 * rb.x; acc[2][1] += ra2 * rb.y; acc[2][2] += ra2 * rb.z; acc[2][3] += ra2 * rb.w;
            acc[3][0] += ra3 * rb.x; acc[3][1] += ra3 * rb.y; acc[3][2] += ra3 * rb.z; acc[3][3] += ra3 * rb.w;
        }
        __syncthreads();
    }

    #pragma unroll
    for (int i = 0; i < 4; i++) {
        int gm = m0 + ty * 4 + i;
        if (gm < Rows) {
            __half2 h0 = __floats2half2_rn(acc[i][0], acc[i][1]);
            __half2 h1 = __floats2half2_rn(acc[i][2], acc[i][3]);
            uint2 u;
            u.x = *(unsigned*)&h0;
            u.y = *(unsigned*)&h1;
            *(uint2*)(C + (long)gm * Ncols + n0 + tx * 4) = u;
        }
    }
}

// ---------------- F=256 gather accumulate, MLP=4, packed index stream ----------------
__device__ __forceinline__ void macc8(float* acc, float4 raw, float v) {
    const __half2* h = (const __half2*)&raw;
    #pragma unroll
    for (int q = 0; q < 4; q++) {
        float2 f = __half22float2(h[q]);
        acc[q * 2 + 0] += v * f.x;
        acc[q * 2 + 1] += v * f.y;
    }
}

__device__ __forceinline__ void accum256(const int2* __restrict__ pack,
                                         int s, int e, const __half* __restrict__ dense,
                                         int lane, float* acc) {
    int j = s;
    if (j + 4 <= e) {
        int2 p0 = __ldg(pack + j),     p1 = __ldg(pack + j + 1);
        int2 p2 = __ldg(pack + j + 2), p3 = __ldg(pack + j + 3);
        for (; j + 4 <= e; ) {
            float4 r0 = ((const float4*)(dense + (long)p0.x * 256))[lane];
            float4 r1 = ((const float4*)(dense + (long)p1.x * 256))[lane];
            float4 r2 = ((const float4*)(dense + (long)p2.x * 256))[lane];
            float4 r3 = ((const float4*)(dense + (long)p3.x * 256))[lane];
            float w0 = __int_as_float(p0.y), w1 = __int_as_float(p1.y);
            float w2 = __int_as_float(p2.y), w3 = __int_as_float(p3.y);
            j += 4;
            if (j + 4 <= e) {
                p0 = __ldg(pack + j);     p1 = __ldg(pack + j + 1);
                p2 = __ldg(pack + j + 2); p3 = __ldg(pack + j + 3);
            }
            macc8(acc, r0, w0);
            macc8(acc, r1, w1);
            macc8(acc, r2, w2);
            macc8(acc, r3, w3);
        }
    }
    for (; j < e; j++) {
        int2 p = __ldg(pack + j);
        float4 r = ((const float4*)(dense + (long)p.x * 256))[lane];
        macc8(acc, r, __int_as_float(p.y));
    }
}

// ---------------- combined F=256 dual SpMM + leaky -> fp16 output ----------------
__global__ void spmm256_all(const int* __restrict__ rp, const int2* __restrict__ pack,
                            const __half* __restrict__ dX, const __half* __restrict__ dY,
                            __half* __restrict__ x1h, __half* __restrict__ y1h) {
    int w = (blockIdx.x * blockDim.x + threadIdx.x) >> 5;
    if (w >= NROWS + MROWS) return;
    int lane = threadIdx.x & 31;

    const int* rpA; const int* rpB; long csA, csB; __half* outp; int r;
    if (w < NROWS) {
        r = w;
        rpA = rp + RP_HHT; csA = CS_HHT;
        rpB = rp + RP_H;   csB = CS_H;
        outp = x1h;
    } else {
        r = w - NROWS;
        rpA = rp + RP_HT;  csA = CS_HT;
        rpB = rp + RP_HTH; csB = CS_HTH;
        outp = y1h;
    }

    float a[8] = {}, b[8] = {};
    accum256(pack + csA, rpA[r], rpA[r + 1], dX, lane, a);
    accum256(pack + csB, rpB[r], rpB[r + 1], dY, lane, b);

    __half2 h[4];
    #pragma unroll
    for (int q = 0; q < 4; q++)
        h[q] = __floats2half2_rn(leaky(a[q * 2]) + leaky(b[q * 2]),
                                 leaky(a[q * 2 + 1]) + leaky(b[q * 2 + 1]));
    uint4 u;
    u.x = *(unsigned*)&h[0]; u.y = *(unsigned*)&h[1];
    u.z = *(unsigned*)&h[2]; u.w = *(unsigned*)&h[3];
    *((uint4*)(outp + (long)r * 256) + lane) = u;
}

// ---------------- F=64 gather accumulate, MLP=4, packed ----------------
__device__ __forceinline__ void accum64(const int2* __restrict__ pack,
                                        int s, int e, const __half* __restrict__ dense,
                                        int lane, float2& acc) {
    int j = s;
    if (j + 4 <= e) {
        int2 p0 = __ldg(pack + j),     p1 = __ldg(pack + j + 1);
        int2 p2 = __ldg(pack + j + 2), p3 = __ldg(pack + j + 3);
        for (; j + 4 <= e; ) {
            __half2 h0 = ((const __half2*)(dense + (long)p0.x * 64))[lane];
            __half2 h1 = ((const __half2*)(dense + (long)p1.x * 64))[lane];
            __half2 h2 = ((const __half2*)(dense + (long)p2.x * 64))[lane];
            __half2 h3 = ((const __half2*)(dense + (long)p3.x * 64))[lane];
            float w0 = __int_as_float(p0.y), w1 = __int_as_float(p1.y);
            float w2 = __int_as_float(p2.y), w3 = __int_as_float(p3.y);
            j += 4;
            if (j + 4 <= e) {
                p0 = __ldg(pack + j);     p1 = __ldg(pack + j + 1);
                p2 = __ldg(pack + j + 2); p3 = __ldg(pack + j + 3);
            }
            float2 f;
            f = __half22float2(h0); acc.x += w0 * f.x; acc.y += w0 * f.y;
            f = __half22float2(h1); acc.x += w1 * f.x; acc.y += w1 * f.y;
            f = __half22float2(h2); acc.x += w2 * f.x; acc.y += w2 * f.y;
            f = __half22float2(h3); acc.x += w3 * f.x; acc.y += w3 * f.y;
        }
    }
    for (; j < e; j++) {
        int2 p = __ldg(pack + j);
        float2 f = __half22float2(((const __half2*)(dense + (long)p.x * 64))[lane]);
        float v = __int_as_float(p.y);
        acc.x += v * f.x; acc.y += v * f.y;
    }
}

// ---------------- combined F=64 dual SpMM + leaky straight into d_out ----------------
__global__ void spmm64_all(const int* __restrict__ rp, const int2* __restrict__ pack,
                           const __half* __restrict__ dX, const __half* __restrict__ dY,
                           float* __restrict__ outbase) {
    int w = (blockIdx.x * blockDim.x + threadIdx.x) >> 5;
    if (w >= NROWS + MROWS) return;
    int lane = threadIdx.x & 31;

    const int* rpA; const int* rpB; long csA, csB; int r;
    if (w < NROWS) {
        r = w;
        rpA = rp + RP_HHT; csA = CS_HHT;
        rpB = rp + RP_H;   csB = CS_H;
    } else {
        r = w - NROWS;
        rpA = rp + RP_HT;  csA = CS_HT;
        rpB = rp + RP_HTH; csB = CS_HTH;
    }

    float2 a = make_float2(0, 0), b = a;
    accum64(pack + csA, rpA[r], rpA[r + 1], dX, lane, a);
    accum64(pack + csB, rpB[r], rpB[r + 1], dY, lane, b);

    float2 res;
    res.x = leaky(a.x) + leaky(b.x);
    res.y = leaky(a.y) + leaky(b.y);
    ((float2*)(outbase + (long)w * 64))[lane] = res;
}

// ---------------- side-stream handles (host objects only; created once) ----------------
static cudaStream_t g_side = nullptr;
static cudaEvent_t  g_fork = nullptr;
static cudaEvent_t  g_join = nullptr;

extern "C" void kernel_launch(void* const* d_in, const int* in_sizes, int n_in,
                              void* d_out, int out_size) {
    const float* x  = (const float*)d_in[0];
    const float* y  = (const float*)d_in[1];
    const float* W0 = (const float*)d_in[2];
    const float* W1 = (const float*)d_in[3];
    const int*   hht_r = (const int*)d_in[4];
    const int*   hht_c = (const int*)d_in[5];
    const float* hht_v = (const float*)d_in[6];
    const int*   h_r = (const int*)d_in[7];
    const int*   h_c = (const int*)d_in[8];
    const float* h_v = (const float*)d_in[9];
    const int*   ht_r = (const int*)d_in[10];
    const int*   ht_c = (const int*)d_in[11];
    const float* ht_v = (const float*)d_in[12];
    const int*   hth_r = (const int*)d_in[13];
    const int*   hth_c = (const int*)d_in[14];
    const float* hth_v = (const float*)d_in[15];
    float* out = (float*)d_out;

    if (!g_side) {
        cudaStreamCreateWithFlags(&g_side, cudaStreamNonBlocking);
        cudaEventCreateWithFlags(&g_fork, cudaEventDisableTiming);
        cudaEventCreateWithFlags(&g_join, cudaEventDisableTiming);
    }

    void* p = nullptr;
    cudaGetSymbolAddress(&p, g_hs);
    __half* H = (__half*)p;
    cudaGetSymbolAddress(&p, g_is);
    int* I = (int*)p;
    cudaGetSymbolAddress(&p, g_pack);
    int2* pack = (int2*)p;

    __half* xw0  = H + H_XW0;
    __half* yw0  = H + H_YW0;
    __half* x1h  = H + H_X1;
    __half* y1h  = H + H_Y1;
    __half* x1w1 = H + H_X1W1;
    __half* y1w1 = H + H_Y1W1;

    int* cur = I + I_CUR;
    int* rp  = I + I_RP;

    const int T = 256;

    // ---- fork: CSR build on side stream, layer-0 GEMM on main stream ----
    cudaEventRecord(g_fork, 0);
    cudaStreamWaitEvent(g_side, g_fork, 0);

    {   // side stream: CSR build
        int ncur = 2 * NROWS + 2 * MROWS;
        zero_i<<<(ncur + T - 1) / T, T, 0, g_side>>>(cur, ncur);
        count_all_k<<<(NNZ_TOT + T - 1) / T, T, 0, g_side>>>(hht_r, h_r, ht_r, hth_r, cur);
        scan_all_k<<<4, 1024, 0, g_side>>>(cur, rp);
        permute_all_k<<<(NNZ_TOT + T - 1) / T, T, 0, g_side>>>(hht_r, hht_c, hht_v,
                                                               h_r, h_c, h_v,
                                                               ht_r, ht_c, ht_v,
                                                               hth_r, hth_c, hth_v,
                                                               cur, pack);
        cudaEventRecord(g_join, g_side);
    }

    {   // main stream: layer-0 GEMMs (fp32 A, fp16 C)
        int nb1 = (NROWS + 63) / 64, nb2 = (MROWS + 63) / 64;
        dim3 g(256 / 64, nb1 + nb2);
        gemm2_k256<0><<<g, T>>>(x, NROWS, y, MROWS, W0, xw0, yw0, 256, nb1);
    }

    // ---- join ----
    cudaStreamWaitEvent(0, g_join, 0);

    // ---- layer-0 SpMM (combined) -> fp16 x1/y1 ----
    spmm256_all<<<(NROWS + MROWS + 7) / 8, T>>>(rp, pack, xw0, yw0, x1h, y1h);

    // ---- layer-1 GEMMs (fp16 A, fp16 C) ----
    {
        int nb1 = (NROWS + 63) / 64, nb2 = (MROWS + 63) / 64;
        dim3 g(64 / 64, nb1 + nb2);
        gemm2_k256<1><<<g, T>>>(x1h, NROWS, y1h, MROWS, W1, x1w1, y1w1, 64, nb1);
    }

    // ---- layer-1 SpMM (combined) straight into d_out ----
    spmm64_all<<<(NROWS + MROWS + 7) / 8, T>>>(rp, pack, x1w1, y1w1, out);
}

// round 8
// speedup vs baseline: 2.6358x; 1.3804x over previous
#include <cuda_runtime.h>
#include <cuda_fp16.h>
#include <cstdint>

// ---------------- problem constants ----------------
#define NROWS 50000
#define MROWS 20000
#define NNZ_HHT 1600000
#define NNZ_H   1000000
#define NNZ_HT  1000000
#define NNZ_HTH 640000
#define NNZ_TOT (NNZ_HHT + NNZ_H + NNZ_HT + NNZ_HTH)
#define NEG_SLOPE 0.2f

// ---------------- half scratch (element counts) ----------------
#define H_XW0   0L
#define H_YW0   (H_XW0  + 12800000L)
#define H_X1    (H_YW0  + 5120000L)
#define H_Y1    (H_X1   + 12800000L)
#define H_X1W1  (H_Y1   + 5120000L)
#define H_Y1W1  (H_X1W1 + 3200000L)
#define HS_TOT  (H_Y1W1 + 1280000L)

// ---------------- int scratch ----------------
#define I_CUR   0L
#define I_RP    (I_CUR + 2L*NROWS + 2L*MROWS)
#define IS_TOT  (I_RP  + 2L*(NROWS+1) + 2L*(MROWS+1))

#define CUR_HHT 0L
#define CUR_H   ((long)NROWS)
#define CUR_HT  (2L*NROWS)
#define CUR_HTH (2L*NROWS + MROWS)
#define RP_HHT  0L
#define RP_H    ((long)NROWS + 1)
#define RP_HT   (2L*(NROWS + 1))
#define RP_HTH  (2L*(NROWS + 1) + MROWS + 1)
#define CS_HHT  0L
#define CS_H    ((long)NNZ_HHT)
#define CS_HT   ((long)NNZ_HHT + NNZ_H)
#define CS_HTH  ((long)NNZ_HHT + NNZ_H + NNZ_HT)

__device__ __align__(16) __half g_hs[HS_TOT];
__device__ __align__(16) int    g_is[IS_TOT];
__device__ __align__(16) int2   g_pack[NNZ_TOT];

__device__ __forceinline__ float leaky(float v) {
    return v >= 0.f ? v : NEG_SLOPE * v;
}

// ---------------- zero ints ----------------
__global__ void zero_i(int* __restrict__ p, int n) {
    int i = blockIdx.x * blockDim.x + threadIdx.x;
    if (i < n) p[i] = 0;
}

// ---------------- CSR build: count ----------------
__global__ void count_all_k(const int* __restrict__ r0, const int* __restrict__ r1,
                            const int* __restrict__ r2, const int* __restrict__ r3,
                            int* __restrict__ cur) {
    long i = (long)blockIdx.x * blockDim.x + threadIdx.x;
    if (i >= NNZ_TOT) return;
    if (i < NNZ_HHT) {
        atomicAdd(&cur[CUR_HHT + r0[i]], 1);
    } else if (i < NNZ_HHT + NNZ_H) {
        atomicAdd(&cur[CUR_H + r1[i - NNZ_HHT]], 1);
    } else if (i < NNZ_HHT + NNZ_H + NNZ_HT) {
        atomicAdd(&cur[CUR_HT + r2[i - NNZ_HHT - NNZ_H]], 1);
    } else {
        atomicAdd(&cur[CUR_HTH + r3[i - NNZ_HHT - NNZ_H - NNZ_HT]], 1);
    }
}

// ---------------- CSR build: fast single-pass scan (4 blocks) ----------------
__global__ void scan_all_k(int* __restrict__ cur, int* __restrict__ rp) {
    __shared__ int wsum[32];
    int b = blockIdx.x;
    int n; int* cnt; int* rowp;
    if (b == 0)      { n = NROWS; cnt = cur + CUR_HHT; rowp = rp + RP_HHT; }
    else if (b == 1) { n = NROWS; cnt = cur + CUR_H;   rowp = rp + RP_H;   }
    else if (b == 2) { n = MROWS; cnt = cur + CUR_HT;  rowp = rp + RP_HT;  }
    else             { n = MROWS; cnt = cur + CUR_HTH; rowp = rp + RP_HTH; }

    int t = threadIdx.x;            // 1024 threads
    int lane = t & 31, wid = t >> 5;
    int CH = (n + 1023) >> 10;
    int s0 = t * CH; if (s0 > n) s0 = n;
    int s1 = s0 + CH; if (s1 > n) s1 = n;

    int sum = 0;
    for (int i = s0; i < s1; i++) sum += cnt[i];

    // warp inclusive scan of per-thread sums
    int v = sum;
    #pragma unroll
    for (int o = 1; o < 32; o <<= 1) {
        int u = __shfl_up_sync(0xffffffffu, v, o);
        if (lane >= o) v += u;
    }
    if (lane == 31) wsum[wid] = v;
    __syncthreads();
    if (wid == 0) {
        int w = wsum[lane];
        #pragma unroll
        for (int o = 1; o < 32; o <<= 1) {
            int u = __shfl_up_sync(0xffffffffu, w, o);
            if (lane >= o) w += u;
        }
        wsum[lane] = w;
    }
    __syncthreads();
    int excl = v - sum + (wid ? wsum[wid - 1] : 0);

    int run = excl;
    for (int i = s0; i < s1; i++) {
        int c = cnt[i];
        rowp[i] = run;
        cnt[i] = run;
        run += c;
    }
    if (t == 1023) rowp[n] = run;
}

// ---------------- CSR build: permute, packed, 2 nnz per thread ----------------
struct Ent { int r, c; float v; long cs; int* cu; };

__device__ __forceinline__ Ent load_ent(long i,
    const int* r0, const int* c0, const float* v0,
    const int* r1, const int* c1, const float* v1,
    const int* r2, const int* c2, const float* v2,
    const int* r3, const int* c3, const float* v3, int* cur) {
    Ent e;
    if (i < NNZ_HHT) {
        e.r = r0[i]; e.c = c0[i]; e.v = v0[i]; e.cs = CS_HHT; e.cu = cur + CUR_HHT;
    } else if (i < NNZ_HHT + NNZ_H) {
        long j = i - NNZ_HHT;
        e.r = r1[j]; e.c = c1[j]; e.v = v1[j]; e.cs = CS_H; e.cu = cur + CUR_H;
    } else if (i < NNZ_HHT + NNZ_H + NNZ_HT) {
        long j = i - NNZ_HHT - NNZ_H;
        e.r = r2[j]; e.c = c2[j]; e.v = v2[j]; e.cs = CS_HT; e.cu = cur + CUR_HT;
    } else {
        long j = i - NNZ_HHT - NNZ_H - NNZ_HT;
        e.r = r3[j]; e.c = c3[j]; e.v = v3[j]; e.cs = CS_HTH; e.cu = cur + CUR_HTH;
    }
    return e;
}

__global__ void permute_all_k(const int* __restrict__ r0, const int* __restrict__ c0, const float* __restrict__ v0,
                              const int* __restrict__ r1, const int* __restrict__ c1, const float* __restrict__ v1,
                              const int* __restrict__ r2, const int* __restrict__ c2, const float* __restrict__ v2,
                              const int* __restrict__ r3, const int* __restrict__ c3, const float* __restrict__ v3,
                              int* __restrict__ cur, int2* __restrict__ pack) {
    long i = ((long)blockIdx.x * blockDim.x + threadIdx.x) * 2;
    if (i >= NNZ_TOT) return;
    Ent e0 = load_ent(i, r0,c0,v0, r1,c1,v1, r2,c2,v2, r3,c3,v3, cur);
    bool two = (i + 1 < NNZ_TOT);
    Ent e1;
    if (two) e1 = load_ent(i + 1, r0,c0,v0, r1,c1,v1, r2,c2,v2, r3,c3,v3, cur);
    int s0 = atomicAdd(&e0.cu[e0.r], 1);
    pack[e0.cs + s0] = make_int2(e0.c, __float_as_int(e0.v));
    if (two) {
        int s1 = atomicAdd(&e1.cu[e1.r], 1);
        pack[e1.cs + s1] = make_int2(e1.c, __float_as_int(e1.v));
    }
}

// ---------------- tensor-core GEMM: C[Rows,Ncols] = A @ W,  K=256 ----------------
// fp16 operands, fp32 accumulate (mma.sync.m16n8k16), C stored fp16.
__device__ __forceinline__ void mma16816(float* c, const unsigned* a, const unsigned* b) {
    asm volatile("mma.sync.aligned.m16n8k16.row.col.f32.f16.f16.f32 "
                 "{%0,%1,%2,%3}, {%4,%5,%6,%7}, {%8,%9}, {%0,%1,%2,%3};"
                 : "+f"(c[0]), "+f"(c[1]), "+f"(c[2]), "+f"(c[3])
                 : "r"(a[0]), "r"(a[1]), "r"(a[2]), "r"(a[3]),
                   "r"(b[0]), "r"(b[1]));
}

template<int AHALF>
__global__ void gemm2_mma(const void* __restrict__ A1v, int Rows1,
                          const void* __restrict__ A2v, int Rows2,
                          const float* __restrict__ W,
                          __half* __restrict__ C1, __half* __restrict__ C2,
                          int Ncols, int nb1) {
    const int BK = 32;
    __shared__ __align__(16) __half As[64][40];   // 80B rows: conflict-free frag loads
    __shared__ __align__(16) __half Bs[64][40];   // Bs[n][k]

    const void* Av;
    __half* C;
    int Rows, m0;
    if ((int)blockIdx.y < nb1) { Av = A1v; C = C1; Rows = Rows1; m0 = blockIdx.y * 64; }
    else                        { Av = A2v; C = C2; Rows = Rows2; m0 = (blockIdx.y - nb1) * 64; }

    int tid = threadIdx.x;         // 256
    int lane = tid & 31, warp = tid >> 5;
    int wm = warp >> 2;            // 0..1 : 32 rows each
    int wn = warp & 3;             // 0..3 : 16 cols each
    int n0 = blockIdx.x * 64;

    float c[2][2][4] = {};

    for (int k0 = 0; k0 < 256; k0 += BK) {
        // --- load A tile 64x32 -> fp16 smem ---
        {
            int m  = tid >> 2;
            int kc = (tid & 3) * 8;
            int gm = m0 + m;
            __half h[8];
            if (gm < Rows) {
                if (AHALF) {
                    const __half* A = (const __half*)Av;
                    *(uint4*)h = *(const uint4*)(A + (long)gm * 256 + k0 + kc);
                } else {
                    const float* A = (const float*)Av;
                    float4 f0 = *(const float4*)(A + (long)gm * 256 + k0 + kc);
                    float4 f1 = *(const float4*)(A + (long)gm * 256 + k0 + kc + 4);
                    h[0] = __float2half(f0.x); h[1] = __float2half(f0.y);
                    h[2] = __float2half(f0.z); h[3] = __float2half(f0.w);
                    h[4] = __float2half(f1.x); h[5] = __float2half(f1.y);
                    h[6] = __float2half(f1.z); h[7] = __float2half(f1.w);
                }
            } else {
                #pragma unroll
                for (int q = 0; q < 8; q++) h[q] = __float2half(0.f);
            }
            *(uint4*)&As[m][kc] = *(uint4*)h;
        }
        // --- load W tile 32x64 transposed -> Bs[n][k] fp16 ---
        {
            int n  = tid & 63;
            int k8 = (tid >> 6) * 8;
            #pragma unroll
            for (int q = 0; q < 8; q++) {
                float w = W[(long)(k0 + k8 + q) * Ncols + n0 + n];
                Bs[n][k8 + q] = __float2half(w);
            }
        }
        __syncthreads();

        #pragma unroll
        for (int ks = 0; ks < 2; ks++) {
            int kk = ks * 16;
            int gr = lane >> 2;
            int gk = (lane & 3) * 2;
            unsigned bf[2][2];
            #pragma unroll
            for (int j = 0; j < 2; j++) {
                int nn = wn * 16 + j * 8 + gr;
                bf[j][0] = *(const unsigned*)&Bs[nn][kk + gk];
                bf[j][1] = *(const unsigned*)&Bs[nn][kk + gk + 8];
            }
            #pragma unroll
            for (int i = 0; i < 2; i++) {
                int r = wm * 32 + i * 16 + gr;
                unsigned a[4];
                a[0] = *(const unsigned*)&As[r][kk + gk];
                a[1] = *(const unsigned*)&As[r + 8][kk + gk];
                a[2] = *(const unsigned*)&As[r][kk + gk + 8];
                a[3] = *(const unsigned*)&As[r + 8][kk + gk + 8];
                mma16816(c[i][0], a, bf[0]);
                mma16816(c[i][1], a, bf[1]);
            }
        }
        __syncthreads();
    }

    // --- epilogue: fp32 acc -> fp16 store ---
    int gr = lane >> 2;
    int gc = (lane & 3) * 2;
    #pragma unroll
    for (int i = 0; i < 2; i++) {
        #pragma unroll
        for (int j = 0; j < 2; j++) {
            int rg = m0 + wm * 32 + i * 16 + gr;
            int cg = n0 + wn * 16 + j * 8 + gc;
            if (rg < Rows) {
                __half2 h = __floats2half2_rn(c[i][j][0], c[i][j][1]);
                *(__half2*)(C + (long)rg * Ncols + cg) = h;
            }
            if (rg + 8 < Rows) {
                __half2 h = __floats2half2_rn(c[i][j][2], c[i][j][3]);
                *(__half2*)(C + (long)(rg + 8) * Ncols + cg) = h;
            }
        }
    }
}

// ---------------- F=256 gather accumulate, MLP=4, packed index stream ----------------
__device__ __forceinline__ void macc8(float* acc, float4 raw, float v) {
    const __half2* h = (const __half2*)&raw;
    #pragma unroll
    for (int q = 0; q < 4; q++) {
        float2 f = __half22float2(h[q]);
        acc[q * 2 + 0] += v * f.x;
        acc[q * 2 + 1] += v * f.y;
    }
}

__device__ __forceinline__ void accum256(const int2* __restrict__ pack,
                                         int s, int e, const __half* __restrict__ dense,
                                         int lane, float* acc) {
    int j = s;
    if (j + 4 <= e) {
        int2 p0 = __ldg(pack + j),     p1 = __ldg(pack + j + 1);
        int2 p2 = __ldg(pack + j + 2), p3 = __ldg(pack + j + 3);
        for (; j + 4 <= e; ) {
            float4 r0 = ((const float4*)(dense + (long)p0.x * 256))[lane];
            float4 r1 = ((const float4*)(dense + (long)p1.x * 256))[lane];
            float4 r2 = ((const float4*)(dense + (long)p2.x * 256))[lane];
            float4 r3 = ((const float4*)(dense + (long)p3.x * 256))[lane];
            float w0 = __int_as_float(p0.y), w1 = __int_as_float(p1.y);
            float w2 = __int_as_float(p2.y), w3 = __int_as_float(p3.y);
            j += 4;
            if (j + 4 <= e) {
                p0 = __ldg(pack + j);     p1 = __ldg(pack + j + 1);
                p2 = __ldg(pack + j + 2); p3 = __ldg(pack + j + 3);
            }
            macc8(acc, r0, w0);
            macc8(acc, r1, w1);
            macc8(acc, r2, w2);
            macc8(acc, r3, w3);
        }
    }
    for (; j < e; j++) {
        int2 p = __ldg(pack + j);
        float4 r = ((const float4*)(dense + (long)p.x * 256))[lane];
        macc8(acc, r, __int_as_float(p.y));
    }
}

// ---------------- combined F=256 dual SpMM + leaky -> fp16 output ----------------
__global__ void spmm256_all(const int* __restrict__ rp, const int2* __restrict__ pack,
                            const __half* __restrict__ dX, const __half* __restrict__ dY,
                            __half* __restrict__ x1h, __half* __restrict__ y1h) {
    int w = (blockIdx.x * blockDim.x + threadIdx.x) >> 5;
    if (w >= NROWS + MROWS) return;
    int lane = threadIdx.x & 31;

    const int* rpA; const int* rpB; long csA, csB; __half* outp; int r;
    if (w < NROWS) {
        r = w;
        rpA = rp + RP_HHT; csA = CS_HHT;
        rpB = rp + RP_H;   csB = CS_H;
        outp = x1h;
    } else {
        r = w - NROWS;
        rpA = rp + RP_HT;  csA = CS_HT;
        rpB = rp + RP_HTH; csB = CS_HTH;
        outp = y1h;
    }

    float a[8] = {}, b[8] = {};
    accum256(pack + csA, rpA[r], rpA[r + 1], dX, lane, a);
    accum256(pack + csB, rpB[r], rpB[r + 1], dY, lane, b);

    __half2 h[4];
    #pragma unroll
    for (int q = 0; q < 4; q++)
        h[q] = __floats2half2_rn(leaky(a[q * 2]) + leaky(b[q * 2]),
                                 leaky(a[q * 2 + 1]) + leaky(b[q * 2 + 1]));
    uint4 u;
    u.x = *(unsigned*)&h[0]; u.y = *(unsigned*)&h[1];
    u.z = *(unsigned*)&h[2]; u.w = *(unsigned*)&h[3];
    *((uint4*)(outp + (long)r * 256) + lane) = u;
}

// ---------------- F=64 gather accumulate, MLP=4, packed ----------------
__device__ __forceinline__ void accum64(const int2* __restrict__ pack,
                                        int s, int e, const __half* __restrict__ dense,
                                        int lane, float2& acc) {
    int j = s;
    if (j + 4 <= e) {
        int2 p0 = __ldg(pack + j),     p1 = __ldg(pack + j + 1);
        int2 p2 = __ldg(pack + j + 2), p3 = __ldg(pack + j + 3);
        for (; j + 4 <= e; ) {
            __half2 h0 = ((const __half2*)(dense + (long)p0.x * 64))[lane];
            __half2 h1 = ((const __half2*)(dense + (long)p1.x * 64))[lane];
            __half2 h2 = ((const __half2*)(dense + (long)p2.x * 64))[lane];
            __half2 h3 = ((const __half2*)(dense + (long)p3.x * 64))[lane];
            float w0 = __int_as_float(p0.y), w1 = __int_as_float(p1.y);
            float w2 = __int_as_float(p2.y), w3 = __int_as_float(p3.y);
            j += 4;
            if (j + 4 <= e) {
                p0 = __ldg(pack + j);     p1 = __ldg(pack + j + 1);
                p2 = __ldg(pack + j + 2); p3 = __ldg(pack + j + 3);
            }
            float2 f;
            f = __half22float2(h0); acc.x += w0 * f.x; acc.y += w0 * f.y;
            f = __half22float2(h1); acc.x += w1 * f.x; acc.y += w1 * f.y;
            f = __half22float2(h2); acc.x += w2 * f.x; acc.y += w2 * f.y;
            f = __half22float2(h3); acc.x += w3 * f.x; acc.y += w3 * f.y;
        }
    }
    for (; j < e; j++) {
        int2 p = __ldg(pack + j);
        float2 f = __half22float2(((const __half2*)(dense + (long)p.x * 64))[lane]);
        float v = __int_as_float(p.y);
        acc.x += v * f.x; acc.y += v * f.y;
    }
}

// ---------------- combined F=64 dual SpMM + leaky straight into d_out ----------------
__global__ void spmm64_all(const int* __restrict__ rp, const int2* __restrict__ pack,
                           const __half* __restrict__ dX, const __half* __restrict__ dY,
                           float* __restrict__ outbase) {
    int w = (blockIdx.x * blockDim.x + threadIdx.x) >> 5;
    if (w >= NROWS + MROWS) return;
    int lane = threadIdx.x & 31;

    const int* rpA; const int* rpB; long csA, csB; int r;
    if (w < NROWS) {
        r = w;
        rpA = rp + RP_HHT; csA = CS_HHT;
        rpB = rp + RP_H;   csB = CS_H;
    } else {
        r = w - NROWS;
        rpA = rp + RP_HT;  csA = CS_HT;
        rpB = rp + RP_HTH; csB = CS_HTH;
    }

    float2 a = make_float2(0, 0), b = a;
    accum64(pack + csA, rpA[r], rpA[r + 1], dX, lane, a);
    accum64(pack + csB, rpB[r], rpB[r + 1], dY, lane, b);

    float2 res;
    res.x = leaky(a.x) + leaky(b.x);
    res.y = leaky(a.y) + leaky(b.y);
    ((float2*)(outbase + (long)w * 64))[lane] = res;
}

// ---------------- side-stream handles ----------------
static cudaStream_t g_side = nullptr;
static cudaEvent_t  g_fork = nullptr;
static cudaEvent_t  g_join = nullptr;

extern "C" void kernel_launch(void* const* d_in, const int* in_sizes, int n_in,
                              void* d_out, int out_size) {
    const float* x  = (const float*)d_in[0];
    const float* y  = (const float*)d_in[1];
    const float* W0 = (const float*)d_in[2];
    const float* W1 = (const float*)d_in[3];
    const int*   hht_r = (const int*)d_in[4];
    const int*   hht_c = (const int*)d_in[5];
    const float* hht_v = (const float*)d_in[6];
    const int*   h_r = (const int*)d_in[7];
    const int*   h_c = (const int*)d_in[8];
    const float* h_v = (const float*)d_in[9];
    const int*   ht_r = (const int*)d_in[10];
    const int*   ht_c = (const int*)d_in[11];
    const float* ht_v = (const float*)d_in[12];
    const int*   hth_r = (const int*)d_in[13];
    const int*   hth_c = (const int*)d_in[14];
    const float* hth_v = (const float*)d_in[15];
    float* out = (float*)d_out;

    if (!g_side) {
        cudaStreamCreateWithFlags(&g_side, cudaStreamNonBlocking);
        cudaEventCreateWithFlags(&g_fork, cudaEventDisableTiming);
        cudaEventCreateWithFlags(&g_join, cudaEventDisableTiming);
    }

    void* p = nullptr;
    cudaGetSymbolAddress(&p, g_hs);
    __half* H = (__half*)p;
    cudaGetSymbolAddress(&p, g_is);
    int* I = (int*)p;
    cudaGetSymbolAddress(&p, g_pack);
    int2* pack = (int2*)p;

    __half* xw0  = H + H_XW0;
    __half* yw0  = H + H_YW0;
    __half* x1h  = H + H_X1;
    __half* y1h  = H + H_Y1;
    __half* x1w1 = H + H_X1W1;
    __half* y1w1 = H + H_Y1W1;

    int* cur = I + I_CUR;
    int* rp  = I + I_RP;

    const int T = 256;

    // ---- fork: CSR build on side stream, layer-0 GEMM on main stream ----
    cudaEventRecord(g_fork, 0);
    cudaStreamWaitEvent(g_side, g_fork, 0);

    {   // side stream: CSR build
        int ncur = 2 * NROWS + 2 * MROWS;
        zero_i<<<(ncur + T - 1) / T, T, 0, g_side>>>(cur, ncur);
        count_all_k<<<(NNZ_TOT + T - 1) / T, T, 0, g_side>>>(hht_r, h_r, ht_r, hth_r, cur);
        scan_all_k<<<4, 1024, 0, g_side>>>(cur, rp);
        permute_all_k<<<(NNZ_TOT / 2 + T - 1) / T, T, 0, g_side>>>(hht_r, hht_c, hht_v,
                                                                   h_r, h_c, h_v,
                                                                   ht_r, ht_c, ht_v,
                                                                   hth_r, hth_c, hth_v,
                                                                   cur, pack);
        cudaEventRecord(g_join, g_side);
    }

    {   // main stream: layer-0 GEMMs (fp32 A -> fp16 mma)
        int nb1 = (NROWS + 63) / 64, nb2 = (MROWS + 63) / 64;
        dim3 g(256 / 64, nb1 + nb2);
        gemm2_mma<0><<<g, T>>>(x, NROWS, y, MROWS, W0, xw0, yw0, 256, nb1);
    }

    // ---- join ----
    cudaStreamWaitEvent(0, g_join, 0);

    // ---- layer-0 SpMM (combined) -> fp16 x1/y1 ----
    spmm256_all<<<(NROWS + MROWS + 7) / 8, T>>>(rp, pack, xw0, yw0, x1h, y1h);

    // ---- layer-1 GEMMs (fp16 A mma) ----
    {
        int nb1 = (NROWS + 63) / 64, nb2 = (MROWS + 63) / 64;
        dim3 g(64 / 64, nb1 + nb2);
        gemm2_mma<1><<<g, T>>>(x1h, NROWS, y1h, MROWS, W1, x1w1, y1w1, 64, nb1);
    }

    // ---- layer-1 SpMM (combined) straight into d_out ----
    spmm64_all<<<(NROWS + MROWS + 7) / 8, T>>>(rp, pack, x1w1, y1w1, out);
}